// round 4
// baseline (speedup 1.0000x reference)
#include <cuda_runtime.h>
#include <math.h>

// Problem dims (fixed)
#define SEQ   512
#define BATCH 64
#define IND   512
#define HID   1024
#define OUTD  512
#define CDIM  1536
#define G4    4096

#define NCTA  128          // recurrence CTAs: CTA n owns j = n*8..n*8+7 (x4 gates)
#define THR   512

// k_recur dynamic smem layout (bytes); all offsets 16B-aligned
#define W_STRIDE 34                          // u64 row stride (272B, 16B-mult)
#define H_STRIDE 66                          // u64 row stride (528B, 16B-mult)
#define W_OFF   0                            // u64[512][34]  = 139264
#define H_OFF   139264                       // u64[8][8][66] = 33792
#define RED_OFF (139264 + 33792)             // float[4][64][33] = 33792 -> 173056
#define CS_OFF  (RED_OFF + 33792)            // float[64][9] = 2304 -> 206848
#define SMEM_RECUR (CS_OFF + 2304)           // 209152

// ---------------- scratch ----------------
__device__ float g_Gx  [(size_t)SEQ * NCTA * BATCH * 32];   // [t][n][b][c], c=q*8+j
__device__ float g_Hall[(size_t)(SEQ + 1) * BATCH * HID];   // h_1..h_S at [t+1]
__device__ int   g_done;                                     // release counter

// ---------------- f32x2 helpers ----------------
typedef unsigned long long u64;
static __device__ __forceinline__ u64 pack2(float x, float y) {
    u64 r; asm("mov.b64 %0, {%1, %2};" : "=l"(r) : "f"(x), "f"(y)); return r;
}
static __device__ __forceinline__ void unpack2(u64 v, float &x, float &y) {
    asm("mov.b64 {%0, %1}, %2;" : "=f"(x), "=f"(y) : "l"(v));
}
static __device__ __forceinline__ u64 fma2(u64 a, u64 b, u64 c) {
    u64 d; asm("fma.rn.f32x2 %0, %1, %2, %3;" : "=l"(d) : "l"(a), "l"(b), "l"(c)); return d;
}
static __device__ __forceinline__ u64 add2(u64 a, u64 b) {
    u64 d; asm("add.rn.f32x2 %0, %1, %2;" : "=l"(d) : "l"(a), "l"(b)); return d;
}
static __device__ __forceinline__ float sigm(float x) { return 1.0f / (1.0f + __expf(-x)); }

__global__ void k_init() { if (threadIdx.x == 0) g_done = 0; }

// =====================================================================
// kernel A: Gx = X @ Wx^T + b, epilogue permuted to [t][n][b][c]
// =====================================================================
__global__ __launch_bounds__(256, 2) void k_pregemm(
    const float* __restrict__ X,
    const float* __restrict__ Wf, const float* __restrict__ bf,
    const float* __restrict__ Wi, const float* __restrict__ bi,
    const float* __restrict__ Wo, const float* __restrict__ bo,
    const float* __restrict__ Wg, const float* __restrict__ bg)
{
    __shared__ u64   xs2[16][130];
    __shared__ float ws [16][132];

    const int tid = threadIdx.x;
    const int m0 = blockIdx.y * 128;
    const int n0 = blockIdx.x * 128;
    const int q  = n0 >> 10;
    const float* Wq = (q == 0) ? Wf : (q == 1) ? Wi : (q == 2) ? Wo : Wg;
    const float* bq = (q == 0) ? bf : (q == 1) ? bi : (q == 2) ? bo : bg;
    const int j0 = n0 & 1023;

    const float* xp[2]; int xm[2], xk4[2];
    const float* wp[2]; int wc[2], wk4[2];
#pragma unroll
    for (int l = 0; l < 2; l++) {
        int e = tid + l * 256;
        int m = e >> 2, k4 = e & 3;
        xp[l] = X + (size_t)(m0 + m) * IND + k4 * 4; xm[l] = m; xk4[l] = k4;
        int c = e >> 2;
        wp[l] = Wq + (size_t)(j0 + c) * CDIM + k4 * 4; wc[l] = c; wk4[l] = k4;
    }

    u64 acc[8][4];
#pragma unroll
    for (int a = 0; a < 8; a++)
#pragma unroll
        for (int b = 0; b < 4; b++) acc[a][b] = 0ull;

    const int mrow = tid >> 4;
    const int ncol = tid & 15;

    float4 rx[2], rw[2];
#pragma unroll
    for (int l = 0; l < 2; l++) { rx[l] = *(const float4*)(xp[l]); rw[l] = *(const float4*)(wp[l]); }

    for (int kc = 0; kc < IND; kc += 16) {
#pragma unroll
        for (int l = 0; l < 2; l++) {
            xs2[xk4[l]*4+0][xm[l]] = pack2(rx[l].x, rx[l].x);
            xs2[xk4[l]*4+1][xm[l]] = pack2(rx[l].y, rx[l].y);
            xs2[xk4[l]*4+2][xm[l]] = pack2(rx[l].z, rx[l].z);
            xs2[xk4[l]*4+3][xm[l]] = pack2(rx[l].w, rx[l].w);
            ws[wk4[l]*4+0][wc[l]] = rw[l].x;
            ws[wk4[l]*4+1][wc[l]] = rw[l].y;
            ws[wk4[l]*4+2][wc[l]] = rw[l].z;
            ws[wk4[l]*4+3][wc[l]] = rw[l].w;
        }
        __syncthreads();
        if (kc + 16 < IND) {
#pragma unroll
            for (int l = 0; l < 2; l++) {
                rx[l] = *(const float4*)(xp[l] + kc + 16);
                rw[l] = *(const float4*)(wp[l] + kc + 16);
            }
        }
#pragma unroll
        for (int kk = 0; kk < 16; kk++) {
            ulonglong2 a01 = *reinterpret_cast<const ulonglong2*>(&xs2[kk][mrow*8 + 0]);
            ulonglong2 a23 = *reinterpret_cast<const ulonglong2*>(&xs2[kk][mrow*8 + 2]);
            ulonglong2 a45 = *reinterpret_cast<const ulonglong2*>(&xs2[kk][mrow*8 + 4]);
            ulonglong2 a67 = *reinterpret_cast<const ulonglong2*>(&xs2[kk][mrow*8 + 6]);
            ulonglong2 w01 = *reinterpret_cast<const ulonglong2*>(&ws[kk][ncol*8 + 0]);
            ulonglong2 w23 = *reinterpret_cast<const ulonglong2*>(&ws[kk][ncol*8 + 4]);
            acc[0][0]=fma2(a01.x,w01.x,acc[0][0]); acc[0][1]=fma2(a01.x,w01.y,acc[0][1]);
            acc[0][2]=fma2(a01.x,w23.x,acc[0][2]); acc[0][3]=fma2(a01.x,w23.y,acc[0][3]);
            acc[1][0]=fma2(a01.y,w01.x,acc[1][0]); acc[1][1]=fma2(a01.y,w01.y,acc[1][1]);
            acc[1][2]=fma2(a01.y,w23.x,acc[1][2]); acc[1][3]=fma2(a01.y,w23.y,acc[1][3]);
            acc[2][0]=fma2(a23.x,w01.x,acc[2][0]); acc[2][1]=fma2(a23.x,w01.y,acc[2][1]);
            acc[2][2]=fma2(a23.x,w23.x,acc[2][2]); acc[2][3]=fma2(a23.x,w23.y,acc[2][3]);
            acc[3][0]=fma2(a23.y,w01.x,acc[3][0]); acc[3][1]=fma2(a23.y,w01.y,acc[3][1]);
            acc[3][2]=fma2(a23.y,w23.x,acc[3][2]); acc[3][3]=fma2(a23.y,w23.y,acc[3][3]);
            acc[4][0]=fma2(a45.x,w01.x,acc[4][0]); acc[4][1]=fma2(a45.x,w01.y,acc[4][1]);
            acc[4][2]=fma2(a45.x,w23.x,acc[4][2]); acc[4][3]=fma2(a45.x,w23.y,acc[4][3]);
            acc[5][0]=fma2(a45.y,w01.x,acc[5][0]); acc[5][1]=fma2(a45.y,w01.y,acc[5][1]);
            acc[5][2]=fma2(a45.y,w23.x,acc[5][2]); acc[5][3]=fma2(a45.y,w23.y,acc[5][3]);
            acc[6][0]=fma2(a67.x,w01.x,acc[6][0]); acc[6][1]=fma2(a67.x,w01.y,acc[6][1]);
            acc[6][2]=fma2(a67.x,w23.x,acc[6][2]); acc[6][3]=fma2(a67.x,w23.y,acc[6][3]);
            acc[7][0]=fma2(a67.y,w01.x,acc[7][0]); acc[7][1]=fma2(a67.y,w01.y,acc[7][1]);
            acc[7][2]=fma2(a67.y,w23.x,acc[7][2]); acc[7][3]=fma2(a67.y,w23.y,acc[7][3]);
        }
        __syncthreads();
    }

    // epilogue: +bias, store permuted [t][n][b][c] (pair stays inside one 8-block)
#pragma unroll
    for (int p = 0; p < 4; p++) {
        int c  = ncol * 8 + p * 2;
        int jj = j0 + c;                    // col within gate 0..1023 (even)
        int nt = jj >> 3, j = jj & 7;
        u64 bb = pack2(bq[jj], bq[jj + 1]);
#pragma unroll
        for (int m = 0; m < 8; m++) {
            int gm = m0 + mrow * 8 + m;
            int tt = gm >> 6, b = gm & 63;
            size_t dst = (((size_t)tt * NCTA + nt) * 64 + b) * 32 + q * 8 + j;
            *reinterpret_cast<u64*>(&g_Gx[dst]) = add2(acc[m][p], bb);
        }
    }
}

// =====================================================================
// kernel B: PERSISTENT recurrence, ONE sync point per step.
// 128 CTAs x 512 thr. CTA n: full-K GEMM for its 32 gate-cols.
// 8 k-groups x 64 threads inside the CTA; smem tree-reduce; c in smem.
// =====================================================================
__global__ __launch_bounds__(THR, 1) void k_recur(
    const float* __restrict__ Wf, const float* __restrict__ Wi,
    const float* __restrict__ Wo, const float* __restrict__ Wg)
{
    extern __shared__ char smem[];
    u64*   wsk  = (u64*)(smem + W_OFF);     // [k2 0..511][c 0..31] stride 34
    u64*   hsk  = (u64*)(smem + H_OFF);     // [kg][k2l 0..7][b 0..63] stride 66
    float* red  = (float*)(smem + RED_OFF); // [buf 0..3][b][c] stride 33
    float* cs   = (float*)(smem + CS_OFF);  // [b][j] stride 9

    const int tid = threadIdx.x;
    const int n   = blockIdx.x;

    // ---- one-time: W slice (32 gate-cols x 1024 k) into smem, K-paired ----
#pragma unroll 4
    for (int i = 0; i < 32; i++) {
        int e  = tid + i * 512;             // 0..16383
        int c  = e & 31, k2 = e >> 5;       // k2 0..511
        int q  = c >> 3, j = c & 7;
        const float* Wq = (q == 0) ? Wf : (q == 1) ? Wi : (q == 2) ? Wo : Wg;
        wsk[(size_t)k2 * W_STRIDE + c] =
            *(const u64*)(Wq + (size_t)(n * 8 + j) * CDIM + IND + k2 * 2);
    }
    // cell state = 0
    cs[(tid >> 3) * 9 + (tid & 7)] = 0.0f;
    __syncthreads();

    // GEMM thread org: kg = k-group (k range kg*128..+127), 64 threads each
    const int kg = tid >> 6;
    const int l  = tid & 63;
    const int b0 = (l >> 3) * 8;            // 8 batch rows
    const int c0 = (l & 7) * 4;             // 4 cols
    u64* hbuf = hsk + kg * (8 * H_STRIDE);
    // activation org
    const int b_act = tid >> 3, j_act = tid & 7;

    for (int t = 0; t < SEQ; t++) {
        // Gx prefetch (independent of h) — issued before the wait
        const float* gxp = g_Gx + (((size_t)t * NCTA + n) * 64 + b_act) * 32 + j_act;
        float gx0 = gxp[0], gx1 = gxp[8], gx2 = gxp[16], gx3 = gxp[24];

        if (t > 0) {
            // ---- wait for all h_t writers (single acquire counter) ----
            if (tid == 0) {
                int target = NCTA * t, v;
                do {
                    asm volatile("ld.acquire.gpu.global.s32 %0, [%1];"
                                 : "=r"(v) : "l"(&g_done) : "memory");
                } while (v < target);
            }
            __syncthreads();

            // ---- GEMM: full K=1024, this kg covers k in [kg*128, kg*128+128) ----
            const u64* hsrc = (const u64*)g_Hall + (size_t)t * 32768 + (size_t)l * 512 + kg * 64;

            u64 acc[8][4];
#pragma unroll
            for (int r = 0; r < 8; r++)
#pragma unroll
                for (int c = 0; c < 4; c++) acc[r][c] = 0ull;

            ulonglong2 p0 = *(const ulonglong2*)(hsrc + 0);
            ulonglong2 p1 = *(const ulonglong2*)(hsrc + 2);
            ulonglong2 p2 = *(const ulonglong2*)(hsrc + 4);
            ulonglong2 p3 = *(const ulonglong2*)(hsrc + 6);

#pragma unroll 1
            for (int ch = 0; ch < 8; ch++) {
                asm volatile("bar.sync %0, %1;" :: "r"(kg + 1), "r"(64) : "memory");
                hbuf[0 * H_STRIDE + l] = p0.x; hbuf[1 * H_STRIDE + l] = p0.y;
                hbuf[2 * H_STRIDE + l] = p1.x; hbuf[3 * H_STRIDE + l] = p1.y;
                hbuf[4 * H_STRIDE + l] = p2.x; hbuf[5 * H_STRIDE + l] = p2.y;
                hbuf[6 * H_STRIDE + l] = p3.x; hbuf[7 * H_STRIDE + l] = p3.y;
                asm volatile("bar.sync %0, %1;" :: "r"(kg + 1), "r"(64) : "memory");
                if (ch < 7) {
                    const u64* nx = hsrc + (ch + 1) * 8;
                    p0 = *(const ulonglong2*)(nx + 0);
                    p1 = *(const ulonglong2*)(nx + 2);
                    p2 = *(const ulonglong2*)(nx + 4);
                    p3 = *(const ulonglong2*)(nx + 6);
                }
                const u64* wrow = wsk + (size_t)(kg * 64 + ch * 8) * W_STRIDE;
#pragma unroll
                for (int kk2 = 0; kk2 < 8; kk2++) {
                    const u64* hp = hbuf + kk2 * H_STRIDE;
                    const u64* wp = wrow + kk2 * W_STRIDE;
                    ulonglong2 h01 = *(const ulonglong2*)(hp + b0 + 0);
                    ulonglong2 h23 = *(const ulonglong2*)(hp + b0 + 2);
                    ulonglong2 h45 = *(const ulonglong2*)(hp + b0 + 4);
                    ulonglong2 h67 = *(const ulonglong2*)(hp + b0 + 6);
                    ulonglong2 wA  = *(const ulonglong2*)(wp + c0 + 0);
                    ulonglong2 wB  = *(const ulonglong2*)(wp + c0 + 2);
                    acc[0][0]=fma2(h01.x,wA.x,acc[0][0]); acc[0][1]=fma2(h01.x,wA.y,acc[0][1]);
                    acc[0][2]=fma2(h01.x,wB.x,acc[0][2]); acc[0][3]=fma2(h01.x,wB.y,acc[0][3]);
                    acc[1][0]=fma2(h01.y,wA.x,acc[1][0]); acc[1][1]=fma2(h01.y,wA.y,acc[1][1]);
                    acc[1][2]=fma2(h01.y,wB.x,acc[1][2]); acc[1][3]=fma2(h01.y,wB.y,acc[1][3]);
                    acc[2][0]=fma2(h23.x,wA.x,acc[2][0]); acc[2][1]=fma2(h23.x,wA.y,acc[2][1]);
                    acc[2][2]=fma2(h23.x,wB.x,acc[2][2]); acc[2][3]=fma2(h23.x,wB.y,acc[2][3]);
                    acc[3][0]=fma2(h23.y,wA.x,acc[3][0]); acc[3][1]=fma2(h23.y,wA.y,acc[3][1]);
                    acc[3][2]=fma2(h23.y,wB.x,acc[3][2]); acc[3][3]=fma2(h23.y,wB.y,acc[3][3]);
                    acc[4][0]=fma2(h45.x,wA.x,acc[4][0]); acc[4][1]=fma2(h45.x,wA.y,acc[4][1]);
                    acc[4][2]=fma2(h45.x,wB.x,acc[4][2]); acc[4][3]=fma2(h45.x,wB.y,acc[4][3]);
                    acc[5][0]=fma2(h45.y,wA.x,acc[5][0]); acc[5][1]=fma2(h45.y,wA.y,acc[5][1]);
                    acc[5][2]=fma2(h45.y,wB.x,acc[5][2]); acc[5][3]=fma2(h45.y,wB.y,acc[5][3]);
                    acc[6][0]=fma2(h67.x,wA.x,acc[6][0]); acc[6][1]=fma2(h67.x,wA.y,acc[6][1]);
                    acc[6][2]=fma2(h67.x,wB.x,acc[6][2]); acc[6][3]=fma2(h67.x,wB.y,acc[6][3]);
                    acc[7][0]=fma2(h67.y,wA.x,acc[7][0]); acc[7][1]=fma2(h67.y,wA.y,acc[7][1]);
                    acc[7][2]=fma2(h67.y,wB.x,acc[7][2]); acc[7][3]=fma2(h67.y,wB.y,acc[7][3]);
                }
            }

            // fold K-pairs -> 32 floats per thread
            float out[8][4];
#pragma unroll
            for (int r = 0; r < 8; r++)
#pragma unroll
                for (int c = 0; c < 4; c++) {
                    float lo, hi; unpack2(acc[r][c], lo, hi); out[r][c] = lo + hi;
                }

            // ---- smem tree reduce over 8 k-groups (4 syncthreads) ----
            if (kg < 4) {
                float* rb = red + (size_t)kg * (64 * 33);
#pragma unroll
                for (int r = 0; r < 8; r++)
#pragma unroll
                    for (int c = 0; c < 4; c++)
                        rb[(b0 + r) * 33 + c0 + c] = out[r][c];
            }
            __syncthreads();
            if (kg >= 4) {
                float* rb = red + (size_t)(kg - 4) * (64 * 33);
#pragma unroll
                for (int r = 0; r < 8; r++)
#pragma unroll
                    for (int c = 0; c < 4; c++)
                        rb[(b0 + r) * 33 + c0 + c] += out[r][c];
            }
            __syncthreads();
#pragma unroll
            for (int i = 0; i < 8; i++) {
                int idx = tid + i * 512;            // 0..4095
                int buf = idx >> 11, e = idx & 2047;
                int b = e >> 5, c = e & 31;
                red[(size_t)buf * (64*33) + b * 33 + c] +=
                    red[(size_t)(buf + 2) * (64*33) + b * 33 + c];
            }
            __syncthreads();
#pragma unroll
            for (int i = 0; i < 4; i++) {
                int e = tid + i * 512;              // 0..2047
                int b = e >> 5, c = e & 31;
                red[b * 33 + c] += red[(size_t)(64*33) + b * 33 + c];
            }
            __syncthreads();
        }

        // ---- fused activations + cell update + h write (this CTA's 8 j, all b) ----
        {
            float fv = gx0, iv = gx1, ov = gx2, gv = gx3;
            if (t > 0) {
                fv += red[b_act * 33 + j_act];
                iv += red[b_act * 33 + 8 + j_act];
                ov += red[b_act * 33 + 16 + j_act];
                gv += red[b_act * 33 + 24 + j_act];
            }
            float f  = sigm(fv), ii = sigm(iv), oo = sigm(ov), gt = tanhf(gv);
            float cprev = cs[b_act * 9 + j_act];
            float cn = f * cprev + ii * gt;
            cs[b_act * 9 + j_act] = cn;
            g_Hall[(size_t)(t + 1) * 65536 + (size_t)b_act * 1024 + n * 8 + j_act]
                = oo * tanhf(cn);
        }

        // ---- single release arrive ----
        __syncthreads();
        if (tid == 0)
            asm volatile("red.release.gpu.global.add.s32 [%0], %1;"
                         :: "l"(&g_done), "r"(1) : "memory");
    }
}

// =====================================================================
// kernel C: out = Hall[1..] @ Wy^T + by   [unchanged]
// =====================================================================
__global__ __launch_bounds__(256, 2) void k_out(
    const float* __restrict__ Wy, const float* __restrict__ by,
    float* __restrict__ Yout)
{
    __shared__ u64   xs2[16][130];
    __shared__ float ws [16][132];

    const int tid = threadIdx.x;
    const int m0 = blockIdx.y * 128;
    const int n0 = blockIdx.x * 128;
    const float* Hsrc = g_Hall + (size_t)(BATCH * HID);

    const float* xp[2]; int xm[2], xk4[2];
    const float* wp[2]; int wc[2], wk4[2];
#pragma unroll
    for (int l = 0; l < 2; l++) {
        int e = tid + l * 256;
        int m = e >> 2, k4 = e & 3;
        xp[l] = Hsrc + (size_t)(m0 + m) * HID + k4 * 4; xm[l] = m; xk4[l] = k4;
        int c = e >> 2;
        wp[l] = Wy + (size_t)(n0 + c) * HID + k4 * 4; wc[l] = c; wk4[l] = k4;
    }

    u64 acc[8][4];
#pragma unroll
    for (int a = 0; a < 8; a++)
#pragma unroll
        for (int b = 0; b < 4; b++) acc[a][b] = 0ull;

    const int mrow = tid >> 4;
    const int ncol = tid & 15;

    float4 rx[2], rw[2];
#pragma unroll
    for (int l = 0; l < 2; l++) { rx[l] = *(const float4*)(xp[l]); rw[l] = *(const float4*)(wp[l]); }

    for (int kc = 0; kc < HID; kc += 16) {
#pragma unroll
        for (int l = 0; l < 2; l++) {
            xs2[xk4[l]*4+0][xm[l]] = pack2(rx[l].x, rx[l].x);
            xs2[xk4[l]*4+1][xm[l]] = pack2(rx[l].y, rx[l].y);
            xs2[xk4[l]*4+2][xm[l]] = pack2(rx[l].z, rx[l].z);
            xs2[xk4[l]*4+3][xm[l]] = pack2(rx[l].w, rx[l].w);
            ws[wk4[l]*4+0][wc[l]] = rw[l].x;
            ws[wk4[l]*4+1][wc[l]] = rw[l].y;
            ws[wk4[l]*4+2][wc[l]] = rw[l].z;
            ws[wk4[l]*4+3][wc[l]] = rw[l].w;
        }
        __syncthreads();
        if (kc + 16 < HID) {
#pragma unroll
            for (int l = 0; l < 2; l++) {
                rx[l] = *(const float4*)(xp[l] + kc + 16);
                rw[l] = *(const float4*)(wp[l] + kc + 16);
            }
        }
#pragma unroll
        for (int kk = 0; kk < 16; kk++) {
            ulonglong2 a01 = *reinterpret_cast<const ulonglong2*>(&xs2[kk][mrow*8 + 0]);
            ulonglong2 a23 = *reinterpret_cast<const ulonglong2*>(&xs2[kk][mrow*8 + 2]);
            ulonglong2 a45 = *reinterpret_cast<const ulonglong2*>(&xs2[kk][mrow*8 + 4]);
            ulonglong2 a67 = *reinterpret_cast<const ulonglong2*>(&xs2[kk][mrow*8 + 6]);
            ulonglong2 w01 = *reinterpret_cast<const ulonglong2*>(&ws[kk][ncol*8 + 0]);
            ulonglong2 w23 = *reinterpret_cast<const ulonglong2*>(&ws[kk][ncol*8 + 4]);
            acc[0][0]=fma2(a01.x,w01.x,acc[0][0]); acc[0][1]=fma2(a01.x,w01.y,acc[0][1]);
            acc[0][2]=fma2(a01.x,w23.x,acc[0][2]); acc[0][3]=fma2(a01.x,w23.y,acc[0][3]);
            acc[1][0]=fma2(a01.y,w01.x,acc[1][0]); acc[1][1]=fma2(a01.y,w01.y,acc[1][1]);
            acc[1][2]=fma2(a01.y,w23.x,acc[1][2]); acc[1][3]=fma2(a01.y,w23.y,acc[1][3]);
            acc[2][0]=fma2(a23.x,w01.x,acc[2][0]); acc[2][1]=fma2(a23.x,w01.y,acc[2][1]);
            acc[2][2]=fma2(a23.x,w23.x,acc[2][2]); acc[2][3]=fma2(a23.x,w23.y,acc[2][3]);
            acc[3][0]=fma2(a23.y,w01.x,acc[3][0]); acc[3][1]=fma2(a23.y,w01.y,acc[3][1]);
            acc[3][2]=fma2(a23.y,w23.x,acc[3][2]); acc[3][3]=fma2(a23.y,w23.y,acc[3][3]);
            acc[4][0]=fma2(a45.x,w01.x,acc[4][0]); acc[4][1]=fma2(a45.x,w01.y,acc[4][1]);
            acc[4][2]=fma2(a45.x,w23.x,acc[4][2]); acc[4][3]=fma2(a45.x,w23.y,acc[4][3]);
            acc[5][0]=fma2(a45.y,w01.x,acc[5][0]); acc[5][1]=fma2(a45.y,w01.y,acc[5][1]);
            acc[5][2]=fma2(a45.y,w23.x,acc[5][2]); acc[5][3]=fma2(a45.y,w23.y,acc[5][3]);
            acc[6][0]=fma2(a67.x,w01.x,acc[6][0]); acc[6][1]=fma2(a67.x,w01.y,acc[6][1]);
            acc[6][2]=fma2(a67.x,w23.x,acc[6][2]); acc[6][3]=fma2(a67.x,w23.y,acc[6][3]);
            acc[7][0]=fma2(a67.y,w01.x,acc[7][0]); acc[7][1]=fma2(a67.y,w01.y,acc[7][1]);
            acc[7][2]=fma2(a67.y,w23.x,acc[7][2]); acc[7][3]=fma2(a67.y,w23.y,acc[7][3]);
        }
        __syncthreads();
    }

#pragma unroll
    for (int p = 0; p < 4; p++) {
        int c = ncol * 8 + p * 2;
        u64 bb = pack2(by[n0 + c], by[n0 + c + 1]);
#pragma unroll
        for (int m = 0; m < 8; m++) {
            size_t row = (size_t)(m0 + mrow * 8 + m);
            *reinterpret_cast<u64*>(&Yout[row * OUTD + n0 + c]) = add2(acc[m][p], bb);
        }
    }
}

// ---------------- launch ----------------
extern "C" void kernel_launch(void* const* d_in, const int* in_sizes, int n_in,
                              void* d_out, int out_size) {
    const float* x  = (const float*)d_in[0];
    const float* Wf = (const float*)d_in[1];
    const float* bf = (const float*)d_in[2];
    const float* Wi = (const float*)d_in[3];
    const float* bi = (const float*)d_in[4];
    const float* Wo = (const float*)d_in[5];
    const float* bo = (const float*)d_in[6];
    const float* Wg = (const float*)d_in[7];
    const float* bg = (const float*)d_in[8];
    const float* Wy = (const float*)d_in[9];
    const float* by = (const float*)d_in[10];
    float* out = (float*)d_out;

    cudaFuncSetAttribute(k_recur, cudaFuncAttributeMaxDynamicSharedMemorySize, SMEM_RECUR);

    k_init<<<1, 32>>>();
    k_pregemm<<<dim3(32, 256), 256>>>(x, Wf, bf, Wi, bi, Wo, bo, Wg, bg);
    k_recur<<<NCTA, THR, SMEM_RECUR>>>(Wf, Wi, Wo, Wg);
    k_out<<<dim3(4, 256), 256>>>(Wy, by, out);
}

// round 5
// speedup vs baseline: 1.0305x; 1.0305x over previous
#include <cuda_runtime.h>
#include <math.h>

// Problem dims (fixed)
#define SEQ   512
#define BATCH 64
#define IND   512
#define HID   1024
#define OUTD  512
#define CDIM  1536
#define G4    4096

#define NCTA  128          // recurrence CTAs: CTA n owns j = n*8..n*8+7 (x4 gates)
#define THR   512

// k_recur dynamic smem (bytes), 16B-aligned offsets
#define W_STRIDE 34                          // u64 row stride (272 B)
#define H_STRIDE 66                          // u64 row stride (528 B)
#define W_OFF   0                            // u64[512][34]       = 139264
#define H_OFF   139264                       // u64[4 kg][16][66]  = 33792
#define RED_OFF (139264 + 33792)             // float[4 kg][64][33]= 33792
#define CS_OFF  (RED_OFF + 33792)            // float[64][9]       = 2304
#define SMEM_RECUR (CS_OFF + 2304)           // 209152

// ---------------- scratch ----------------
__device__ float g_Gx  [(size_t)SEQ * NCTA * BATCH * 32];   // [t][n][b][c], c=q*8+j
__device__ float g_Hall[(size_t)(SEQ + 1) * BATCH * HID];   // h_t at [t]
__device__ int   g_done;

// ---------------- f32x2 helpers ----------------
typedef unsigned long long u64;
static __device__ __forceinline__ u64 pack2(float x, float y) {
    u64 r; asm("mov.b64 %0, {%1, %2};" : "=l"(r) : "f"(x), "f"(y)); return r;
}
static __device__ __forceinline__ void unpack2(u64 v, float &x, float &y) {
    asm("mov.b64 {%0, %1}, %2;" : "=f"(x), "=f"(y) : "l"(v));
}
static __device__ __forceinline__ u64 fma2(u64 a, u64 b, u64 c) {
    u64 d; asm("fma.rn.f32x2 %0, %1, %2, %3;" : "=l"(d) : "l"(a), "l"(b), "l"(c)); return d;
}
static __device__ __forceinline__ float fold(u64 v) {
    float lo, hi; unpack2(v, lo, hi); return lo + hi;
}
static __device__ __forceinline__ float sigm(float x) { return 1.0f / (1.0f + __expf(-x)); }

__global__ void k_init() { if (threadIdx.x == 0) g_done = 0; }

// =====================================================================
// kernel A: Gx = X @ Wx^T + b  (M=32768, N=4096, K=512), K-paired FFMA2
// block 128m x 128n, 512 thr, thread tile 8m x 4n, epilogue -> [t][n][b][c]
// =====================================================================
__global__ __launch_bounds__(512, 1) void k_pregemm(
    const float* __restrict__ X,
    const float* __restrict__ Wf, const float* __restrict__ bf,
    const float* __restrict__ Wi, const float* __restrict__ bi,
    const float* __restrict__ Wo, const float* __restrict__ bo,
    const float* __restrict__ Wg, const float* __restrict__ bg)
{
    __shared__ u64 xs2[16][130];   // [k2][m] : (x[m,2k],x[m,2k+1])
    __shared__ u64 ws2[16][130];   // [k2][n] : (w[n,2k],w[n,2k+1])

    const int tid = threadIdx.x;
    const int m0 = blockIdx.y * 128;
    const int n0 = blockIdx.x * 128;
    const int q  = n0 >> 10;
    const float* Wq = (q == 0) ? Wf : (q == 1) ? Wi : (q == 2) ? Wo : Wg;
    const float* bq = (q == 0) ? bf : (q == 1) ? bi : (q == 2) ? bo : bg;
    const int j0 = n0 & 1023;

    // loader: thread loads 2x16B of x (row lm) and 2x16B of w (row lm)
    const int lm = tid >> 2;         // 0..127 (row within tile)
    const int ks = tid & 3;          // k-slot: k2 = ks*4 + 0..3
    const float* xp = X  + (size_t)(m0 + lm) * IND  + ks * 8;
    const float* wp = Wq + (size_t)(j0 + lm) * CDIM + ks * 8;

    u64 acc[8][4];
#pragma unroll
    for (int r = 0; r < 8; r++)
#pragma unroll
        for (int c = 0; c < 4; c++) acc[r][c] = 0ull;

    const int m0t = (tid >> 5) * 8;  // 16 m-groups
    const int n0t = (tid & 31) * 4;  // 32 n-groups

    ulonglong2 px0 = *(const ulonglong2*)(xp);
    ulonglong2 px1 = *(const ulonglong2*)(xp + 4);
    ulonglong2 pw0 = *(const ulonglong2*)(wp);
    ulonglong2 pw1 = *(const ulonglong2*)(wp + 4);

    for (int kc = 0; kc < IND; kc += 32) {       // 16 chunks of 16 k2
        __syncthreads();
        xs2[ks*4+0][lm] = px0.x; xs2[ks*4+1][lm] = px0.y;
        xs2[ks*4+2][lm] = px1.x; xs2[ks*4+3][lm] = px1.y;
        ws2[ks*4+0][lm] = pw0.x; ws2[ks*4+1][lm] = pw0.y;
        ws2[ks*4+2][lm] = pw1.x; ws2[ks*4+3][lm] = pw1.y;
        __syncthreads();
        if (kc + 32 < IND) {
            px0 = *(const ulonglong2*)(xp + kc + 32);
            px1 = *(const ulonglong2*)(xp + kc + 36);
            pw0 = *(const ulonglong2*)(wp + kc + 32);
            pw1 = *(const ulonglong2*)(wp + kc + 36);
        }
#pragma unroll
        for (int kk = 0; kk < 16; kk++) {
            ulonglong2 x01 = *(const ulonglong2*)(&xs2[kk][m0t + 0]);
            ulonglong2 x23 = *(const ulonglong2*)(&xs2[kk][m0t + 2]);
            ulonglong2 x45 = *(const ulonglong2*)(&xs2[kk][m0t + 4]);
            ulonglong2 x67 = *(const ulonglong2*)(&xs2[kk][m0t + 6]);
            ulonglong2 wA  = *(const ulonglong2*)(&ws2[kk][n0t + 0]);
            ulonglong2 wB  = *(const ulonglong2*)(&ws2[kk][n0t + 2]);
            acc[0][0]=fma2(x01.x,wA.x,acc[0][0]); acc[0][1]=fma2(x01.x,wA.y,acc[0][1]);
            acc[0][2]=fma2(x01.x,wB.x,acc[0][2]); acc[0][3]=fma2(x01.x,wB.y,acc[0][3]);
            acc[1][0]=fma2(x01.y,wA.x,acc[1][0]); acc[1][1]=fma2(x01.y,wA.y,acc[1][1]);
            acc[1][2]=fma2(x01.y,wB.x,acc[1][2]); acc[1][3]=fma2(x01.y,wB.y,acc[1][3]);
            acc[2][0]=fma2(x23.x,wA.x,acc[2][0]); acc[2][1]=fma2(x23.x,wA.y,acc[2][1]);
            acc[2][2]=fma2(x23.x,wB.x,acc[2][2]); acc[2][3]=fma2(x23.x,wB.y,acc[2][3]);
            acc[3][0]=fma2(x23.y,wA.x,acc[3][0]); acc[3][1]=fma2(x23.y,wA.y,acc[3][1]);
            acc[3][2]=fma2(x23.y,wB.x,acc[3][2]); acc[3][3]=fma2(x23.y,wB.y,acc[3][3]);
            acc[4][0]=fma2(x45.x,wA.x,acc[4][0]); acc[4][1]=fma2(x45.x,wA.y,acc[4][1]);
            acc[4][2]=fma2(x45.x,wB.x,acc[4][2]); acc[4][3]=fma2(x45.x,wB.y,acc[4][3]);
            acc[5][0]=fma2(x45.y,wA.x,acc[5][0]); acc[5][1]=fma2(x45.y,wA.y,acc[5][1]);
            acc[5][2]=fma2(x45.y,wB.x,acc[5][2]); acc[5][3]=fma2(x45.y,wB.y,acc[5][3]);
            acc[6][0]=fma2(x67.x,wA.x,acc[6][0]); acc[6][1]=fma2(x67.x,wA.y,acc[6][1]);
            acc[6][2]=fma2(x67.x,wB.x,acc[6][2]); acc[6][3]=fma2(x67.x,wB.y,acc[6][3]);
            acc[7][0]=fma2(x67.y,wA.x,acc[7][0]); acc[7][1]=fma2(x67.y,wA.y,acc[7][1]);
            acc[7][2]=fma2(x67.y,wB.x,acc[7][2]); acc[7][3]=fma2(x67.y,wB.y,acc[7][3]);
        }
    }

    // epilogue: fold + bias, float4 store to g_Gx[t][nt][b][q*8+jloc]
    const int jj0 = j0 + n0t;               // first gate-col (mult of 4)
    const int nt  = jj0 >> 3;
    const int jl  = jj0 & 7;                // 0 or 4
    float4 bias = *(const float4*)(bq + jj0);
#pragma unroll
    for (int r = 0; r < 8; r++) {
        int gm = m0 + m0t + r;
        int tt = gm >> 6, b = gm & 63;
        float4 v;
        v.x = fold(acc[r][0]) + bias.x;
        v.y = fold(acc[r][1]) + bias.y;
        v.z = fold(acc[r][2]) + bias.z;
        v.w = fold(acc[r][3]) + bias.w;
        *(float4*)(g_Gx + (((size_t)tt * NCTA + nt) * 64 + b) * 32 + q * 8 + jl) = v;
    }
}

// =====================================================================
// kernel B: PERSISTENT recurrence. 128 CTAs x 512 thr.
// 4 k-groups x 128 thr; thread tile 4b x 4c (32 acc regs, no spills).
// Warp-cooperative h loads (nL=4). One global sync point per step.
// =====================================================================
__global__ __launch_bounds__(THR, 1) void k_recur(
    const float* __restrict__ Wf, const float* __restrict__ Wi,
    const float* __restrict__ Wo, const float* __restrict__ Wg)
{
    extern __shared__ char smem[];
    u64*   wsk = (u64*)(smem + W_OFF);      // [k2 0..511][c 0..31] stride 34
    u64*   hsk = (u64*)(smem + H_OFF);      // [kg][k2l 0..15][b 0..63] stride 66
    float* red = (float*)(smem + RED_OFF);  // [kg][b][c] stride 33
    float* cs  = (float*)(smem + CS_OFF);   // [b][j] stride 9

    const int tid = threadIdx.x;
    const int n   = blockIdx.x;

    // ---- one-time: W slice (32 gate-cols x K=1024) into smem, K-paired ----
#pragma unroll 4
    for (int i = 0; i < 32; i++) {
        int e = tid + i * 512;              // 0..16383
        int c = e & 31, k2 = e >> 5;
        int q = c >> 3, j = c & 7;
        const float* Wq = (q == 0) ? Wf : (q == 1) ? Wi : (q == 2) ? Wo : Wg;
        wsk[(size_t)k2 * W_STRIDE + c] =
            *(const u64*)(Wq + (size_t)(n * 8 + j) * CDIM + IND + k2 * 2);
    }
    cs[(tid >> 3) * 9 + (tid & 7)] = 0.0f;
    __syncthreads();

    const int kg  = tid >> 7;               // 0..3, k2 range [kg*128, kg*128+128)
    const int l   = tid & 127;
    const int ww  = (tid >> 5) & 3;         // warp within kg
    const int lam = tid & 31;
    const int b0  = (l >> 3) * 4;           // 4 batch rows
    const int c0  = (l & 7) * 4;            // 4 gate-cols
    u64* hbuf = hsk + kg * (16 * H_STRIDE);
    const int b_act = tid >> 3, j_act = tid & 7;

    // h loader geometry: 8 lanes per row, 4 rows per instruction
    const int lrow0 = ww * 16 + (lam >> 3); // + i*4
    const int lk2   = (lam & 7) * 2;        // k2l within chunk

    volatile int* vdone = (volatile int*)&g_done;

    for (int t = 0; t < SEQ; t++) {
        // Gx prefetch (independent of h), before the wait
        const float* gxp = g_Gx + (((size_t)t * NCTA + n) * 64 + b_act) * 32 + j_act;
        float gx0 = gxp[0], gx1 = gxp[8], gx2 = gxp[16], gx3 = gxp[24];

        if (t > 0) {
            if (tid == 0) {
                int target = NCTA * t, v;
                do {
                    asm volatile("ld.acquire.gpu.global.s32 %0, [%1];"
                                 : "=r"(v) : "l"(&g_done) : "memory");
                } while (v < target);
            }
            __syncthreads();

            const u64* hbase = (const u64*)g_Hall + (size_t)t * 32768 + kg * 128 + lk2;

            u64 acc[4][4];
#pragma unroll
            for (int r = 0; r < 4; r++)
#pragma unroll
                for (int c = 0; c < 4; c++) acc[r][c] = 0ull;

            // prefetch chunk 0 (warp-cooperative: rows lrow0+4i)
            ulonglong2 pf[4];
#pragma unroll
            for (int i = 0; i < 4; i++)
                pf[i] = *(const ulonglong2*)(hbase + (size_t)(lrow0 + i * 4) * 512);

#pragma unroll 1
            for (int ch = 0; ch < 8; ch++) {
                asm volatile("bar.sync %0, %1;" :: "r"(kg + 1), "r"(128) : "memory");
#pragma unroll
                for (int i = 0; i < 4; i++) {
                    int r = lrow0 + i * 4;
                    hbuf[(lk2 + 0) * H_STRIDE + r] = pf[i].x;
                    hbuf[(lk2 + 1) * H_STRIDE + r] = pf[i].y;
                }
                asm volatile("bar.sync %0, %1;" :: "r"(kg + 1), "r"(128) : "memory");
                if (ch < 7) {
                    const u64* nxt = hbase + (ch + 1) * 16;
#pragma unroll
                    for (int i = 0; i < 4; i++)
                        pf[i] = *(const ulonglong2*)(nxt + (size_t)(lrow0 + i * 4) * 512);
                }
                const u64* wrow = wsk + (size_t)(kg * 128 + ch * 16) * W_STRIDE;
#pragma unroll
                for (int kk2 = 0; kk2 < 16; kk2++) {
                    const u64* hp = hbuf + kk2 * H_STRIDE;
                    const u64* wp = wrow + kk2 * W_STRIDE;
                    ulonglong2 h01 = *(const ulonglong2*)(hp + b0);
                    ulonglong2 h23 = *(const ulonglong2*)(hp + b0 + 2);
                    ulonglong2 wA  = *(const ulonglong2*)(wp + c0);
                    ulonglong2 wB  = *(const ulonglong2*)(wp + c0 + 2);
                    acc[0][0]=fma2(h01.x,wA.x,acc[0][0]); acc[0][1]=fma2(h01.x,wA.y,acc[0][1]);
                    acc[0][2]=fma2(h01.x,wB.x,acc[0][2]); acc[0][3]=fma2(h01.x,wB.y,acc[0][3]);
                    acc[1][0]=fma2(h01.y,wA.x,acc[1][0]); acc[1][1]=fma2(h01.y,wA.y,acc[1][1]);
                    acc[1][2]=fma2(h01.y,wB.x,acc[1][2]); acc[1][3]=fma2(h01.y,wB.y,acc[1][3]);
                    acc[2][0]=fma2(h23.x,wA.x,acc[2][0]); acc[2][1]=fma2(h23.x,wA.y,acc[2][1]);
                    acc[2][2]=fma2(h23.x,wB.x,acc[2][2]); acc[2][3]=fma2(h23.x,wB.y,acc[2][3]);
                    acc[3][0]=fma2(h23.y,wA.x,acc[3][0]); acc[3][1]=fma2(h23.y,wA.y,acc[3][1]);
                    acc[3][2]=fma2(h23.y,wB.x,acc[3][2]); acc[3][3]=fma2(h23.y,wB.y,acc[3][3]);
                }
            }

            // fold + store to this kg's red buffer (no cross-kg ordering needed)
            float* rb = red + (size_t)kg * (64 * 33);
#pragma unroll
            for (int r = 0; r < 4; r++) {
#pragma unroll
                for (int c = 0; c < 4; c++)
                    rb[(b0 + r) * 33 + c0 + c] = fold(acc[r][c]);
            }
            __syncthreads();
        }

        // ---- fused activations + cell update + h write ----
        {
            float fv = gx0, iv = gx1, ov = gx2, gv = gx3;
            if (t > 0) {
                const float* rr = red + b_act * 33 + j_act;
#pragma unroll
                for (int g = 0; g < 4; g++) {
                    fv += rr[g * 2112];
                    iv += rr[g * 2112 + 8];
                    ov += rr[g * 2112 + 16];
                    gv += rr[g * 2112 + 24];
                }
            }
            float f  = sigm(fv), ii = sigm(iv), oo = sigm(ov), gt = tanhf(gv);
            float cprev = cs[b_act * 9 + j_act];
            float cn = f * cprev + ii * gt;
            cs[b_act * 9 + j_act] = cn;
            g_Hall[(size_t)(t + 1) * 65536 + (size_t)b_act * 1024 + n * 8 + j_act]
                = oo * tanhf(cn);
        }

        __syncthreads();
        if (tid == 0)
            asm volatile("red.release.gpu.global.add.s32 [%0], %1;"
                         :: "l"(&g_done), "r"(1) : "memory");
        (void)vdone;
    }
}

// =====================================================================
// kernel C: out = Hall[1..] @ Wy^T + by   (unchanged, proven)
// =====================================================================
__global__ __launch_bounds__(256, 2) void k_out(
    const float* __restrict__ Wy, const float* __restrict__ by,
    float* __restrict__ Yout)
{
    __shared__ u64   xs2[16][130];
    __shared__ float ws [16][132];

    const int tid = threadIdx.x;
    const int m0 = blockIdx.y * 128;
    const int n0 = blockIdx.x * 128;
    const float* Hsrc = g_Hall + (size_t)(BATCH * HID);

    const float* xp[2]; int xm[2], xk4[2];
    const float* wp[2]; int wc[2], wk4[2];
#pragma unroll
    for (int l = 0; l < 2; l++) {
        int e = tid + l * 256;
        int m = e >> 2, k4 = e & 3;
        xp[l] = Hsrc + (size_t)(m0 + m) * HID + k4 * 4; xm[l] = m; xk4[l] = k4;
        int c = e >> 2;
        wp[l] = Wy + (size_t)(n0 + c) * HID + k4 * 4; wc[l] = c; wk4[l] = k4;
    }

    u64 acc[8][4];
#pragma unroll
    for (int a = 0; a < 8; a++)
#pragma unroll
        for (int b = 0; b < 4; b++) acc[a][b] = 0ull;

    const int mrow = tid >> 4;
    const int ncol = tid & 15;

    float4 rx[2], rw[2];
#pragma unroll
    for (int l = 0; l < 2; l++) { rx[l] = *(const float4*)(xp[l]); rw[l] = *(const float4*)(wp[l]); }

    for (int kc = 0; kc < HID; kc += 16) {
#pragma unroll
        for (int l = 0; l < 2; l++) {
            xs2[xk4[l]*4+0][xm[l]] = pack2(rx[l].x, rx[l].x);
            xs2[xk4[l]*4+1][xm[l]] = pack2(rx[l].y, rx[l].y);
            xs2[xk4[l]*4+2][xm[l]] = pack2(rx[l].z, rx[l].z);
            xs2[xk4[l]*4+3][xm[l]] = pack2(rx[l].w, rx[l].w);
            ws[wk4[l]*4+0][wc[l]] = rw[l].x;
            ws[wk4[l]*4+1][wc[l]] = rw[l].y;
            ws[wk4[l]*4+2][wc[l]] = rw[l].z;
            ws[wk4[l]*4+3][wc[l]] = rw[l].w;
        }
        __syncthreads();
        if (kc + 16 < HID) {
#pragma unroll
            for (int l = 0; l < 2; l++) {
                rx[l] = *(const float4*)(xp[l] + kc + 16);
                rw[l] = *(const float4*)(wp[l] + kc + 16);
            }
        }
#pragma unroll
        for (int kk = 0; kk < 16; kk++) {
            ulonglong2 a01 = *reinterpret_cast<const ulonglong2*>(&xs2[kk][mrow*8 + 0]);
            ulonglong2 a23 = *reinterpret_cast<const ulonglong2*>(&xs2[kk][mrow*8 + 2]);
            ulonglong2 a45 = *reinterpret_cast<const ulonglong2*>(&xs2[kk][mrow*8 + 4]);
            ulonglong2 a67 = *reinterpret_cast<const ulonglong2*>(&xs2[kk][mrow*8 + 6]);
            ulonglong2 w01 = *reinterpret_cast<const ulonglong2*>(&ws[kk][ncol*8 + 0]);
            ulonglong2 w23 = *reinterpret_cast<const ulonglong2*>(&ws[kk][ncol*8 + 4]);
            acc[0][0]=fma2(a01.x,w01.x,acc[0][0]); acc[0][1]=fma2(a01.x,w01.y,acc[0][1]);
            acc[0][2]=fma2(a01.x,w23.x,acc[0][2]); acc[0][3]=fma2(a01.x,w23.y,acc[0][3]);
            acc[1][0]=fma2(a01.y,w01.x,acc[1][0]); acc[1][1]=fma2(a01.y,w01.y,acc[1][1]);
            acc[1][2]=fma2(a01.y,w23.x,acc[1][2]); acc[1][3]=fma2(a01.y,w23.y,acc[1][3]);
            acc[2][0]=fma2(a23.x,w01.x,acc[2][0]); acc[2][1]=fma2(a23.x,w01.y,acc[2][1]);
            acc[2][2]=fma2(a23.x,w23.x,acc[2][2]); acc[2][3]=fma2(a23.x,w23.y,acc[2][3]);
            acc[3][0]=fma2(a23.y,w01.x,acc[3][0]); acc[3][1]=fma2(a23.y,w01.y,acc[3][1]);
            acc[3][2]=fma2(a23.y,w23.x,acc[3][2]); acc[3][3]=fma2(a23.y,w23.y,acc[3][3]);
            acc[4][0]=fma2(a45.x,w01.x,acc[4][0]); acc[4][1]=fma2(a45.x,w01.y,acc[4][1]);
            acc[4][2]=fma2(a45.x,w23.x,acc[4][2]); acc[4][3]=fma2(a45.x,w23.y,acc[4][3]);
            acc[5][0]=fma2(a45.y,w01.x,acc[5][0]); acc[5][1]=fma2(a45.y,w01.y,acc[5][1]);
            acc[5][2]=fma2(a45.y,w23.x,acc[5][2]); acc[5][3]=fma2(a45.y,w23.y,acc[5][3]);
            acc[6][0]=fma2(a67.x,w01.x,acc[6][0]); acc[6][1]=fma2(a67.x,w01.y,acc[6][1]);
            acc[6][2]=fma2(a67.x,w23.x,acc[6][2]); acc[6][3]=fma2(a67.x,w23.y,acc[6][3]);
            acc[7][0]=fma2(a67.y,w01.x,acc[7][0]); acc[7][1]=fma2(a67.y,w01.y,acc[7][1]);
            acc[7][2]=fma2(a67.y,w23.x,acc[7][2]); acc[7][3]=fma2(a67.y,w23.y,acc[7][3]);
        }
        __syncthreads();
    }

#pragma unroll
    for (int p = 0; p < 4; p++) {
        int c = ncol * 8 + p * 2;
        u64 bb = pack2(by[n0 + c], by[n0 + c + 1]);
#pragma unroll
        for (int m = 0; m < 8; m++) {
            size_t row = (size_t)(m0 + mrow * 8 + m);
            float lo, hi; unpack2(acc[m][p], lo, hi);
            float blo, bhi; unpack2(bb, blo, bhi);
            Yout[row * OUTD + n0 + c]     = lo + blo;
            Yout[row * OUTD + n0 + c + 1] = hi + bhi;
        }
    }
}

// ---------------- launch ----------------
extern "C" void kernel_launch(void* const* d_in, const int* in_sizes, int n_in,
                              void* d_out, int out_size) {
    const float* x  = (const float*)d_in[0];
    const float* Wf = (const float*)d_in[1];
    const float* bf = (const float*)d_in[2];
    const float* Wi = (const float*)d_in[3];
    const float* bi = (const float*)d_in[4];
    const float* Wo = (const float*)d_in[5];
    const float* bo = (const float*)d_in[6];
    const float* Wg = (const float*)d_in[7];
    const float* bg = (const float*)d_in[8];
    const float* Wy = (const float*)d_in[9];
    const float* by = (const float*)d_in[10];
    float* out = (float*)d_out;

    cudaFuncSetAttribute(k_recur, cudaFuncAttributeMaxDynamicSharedMemorySize, SMEM_RECUR);

    k_init<<<1, 32>>>();
    k_pregemm<<<dim3(32, 256), 512>>>(x, Wf, bf, Wi, bi, Wo, bo, Wg, bg);
    k_recur<<<NCTA, THR, SMEM_RECUR>>>(Wf, Wi, Wo, Wg);
    k_out<<<dim3(4, 256), 256>>>(Wy, by, out);
}

// round 7
// speedup vs baseline: 1.2114x; 1.1755x over previous
#include <cuda_runtime.h>
#include <cuda_bf16.h>
#include <math.h>
#include <stdint.h>

// Problem dims (fixed)
#define SEQ   512
#define BATCH 64
#define IND   512
#define HID   1024
#define OUTD  512
#define CDIM  1536

#define NCTA  128          // recurrence CTAs
#define THR   512

// ---- k_recur smem layout (unchanged from R5 — passing) ----
#define W_STRIDE 34
#define H_STRIDE 66
#define W_OFF   0
#define H_OFF   139264
#define RED_OFF (139264 + 33792)
#define CS_OFF  (RED_OFF + 33792)
#define SMEM_RECUR (CS_OFF + 2304)

typedef unsigned long long u64;

// ---------------- scratch ----------------
__device__ float g_Gx  [(size_t)SEQ * NCTA * BATCH * 32];   // [t][n][b][c]
__device__ float g_Hall[(size_t)(SEQ + 1) * BATCH * HID];
__device__ int   g_done;
__device__ __nv_bfloat16 g_Xhi [(size_t)SEQ * BATCH * IND];
__device__ __nv_bfloat16 g_Xlo [(size_t)SEQ * BATCH * IND];
__device__ __nv_bfloat16 g_WAhi[(size_t)4096 * 512];
__device__ __nv_bfloat16 g_WAlo[(size_t)4096 * 512];
__device__ __nv_bfloat16 g_Hhi [(size_t)SEQ * BATCH * HID];
__device__ __nv_bfloat16 g_Hlo [(size_t)SEQ * BATCH * HID];
__device__ __nv_bfloat16 g_Wyhi[(size_t)OUTD * HID];
__device__ __nv_bfloat16 g_Wylo[(size_t)OUTD * HID];
__device__ float g_ball[4096];

// ---------------- f32x2 helpers (recurrence) ----------------
static __device__ __forceinline__ u64 pack2(float x, float y) {
    u64 r; asm("mov.b64 %0, {%1, %2};" : "=l"(r) : "f"(x), "f"(y)); return r;
}
static __device__ __forceinline__ void unpack2(u64 v, float &x, float &y) {
    asm("mov.b64 {%0, %1}, %2;" : "=f"(x), "=f"(y) : "l"(v));
}
static __device__ __forceinline__ u64 fma2(u64 a, u64 b, u64 c) {
    u64 d; asm("fma.rn.f32x2 %0, %1, %2, %3;" : "=l"(d) : "l"(a), "l"(b), "l"(c)); return d;
}
static __device__ __forceinline__ float fold(u64 v) {
    float lo, hi; unpack2(v, lo, hi); return lo + hi;
}
static __device__ __forceinline__ float sigm(float x) { return 1.0f / (1.0f + __expf(-x)); }

// ---------------- mma.sync helpers ----------------
static __device__ __forceinline__ uint32_t smem_u32(const void* p) {
    uint32_t a;
    asm("{ .reg .u64 t; cvta.to.shared.u64 t, %1; cvt.u32.u64 %0, t; }" : "=r"(a) : "l"(p));
    return a;
}
static __device__ __forceinline__ void ldmx4(uint32_t* r, uint32_t addr) {
    asm volatile("ldmatrix.sync.aligned.m8n8.x4.shared.b16 {%0,%1,%2,%3}, [%4];"
                 : "=r"(r[0]), "=r"(r[1]), "=r"(r[2]), "=r"(r[3]) : "r"(addr));
}
static __device__ __forceinline__ void mma_bf16(float* c, const uint32_t* a, const uint32_t* b) {
    asm volatile(
        "mma.sync.aligned.m16n8k16.row.col.f32.bf16.bf16.f32 "
        "{%0,%1,%2,%3}, {%4,%5,%6,%7}, {%8,%9}, {%0,%1,%2,%3};"
        : "+f"(c[0]), "+f"(c[1]), "+f"(c[2]), "+f"(c[3])
        : "r"(a[0]), "r"(a[1]), "r"(a[2]), "r"(a[3]), "r"(b[0]), "r"(b[1]));
}

__global__ void k_init() { if (threadIdx.x == 0) g_done = 0; }

// =====================================================================
// converters: fp32 -> (bf16 hi, bf16 lo). which: 0=X, 1=Wy, 2=H
// =====================================================================
__global__ void k_cvt(const float4* __restrict__ srcArg, long n4, int which)
{
    u64 *hi, *lo;
    const float4* src = srcArg;
    if (which == 0)      { hi = (u64*)g_Xhi;  lo = (u64*)g_Xlo;  }
    else if (which == 1) { hi = (u64*)g_Wyhi; lo = (u64*)g_Wylo; }
    else                 { hi = (u64*)g_Hhi;  lo = (u64*)g_Hlo;
                           src = (const float4*)(g_Hall + BATCH * HID); }
    long i = (long)blockIdx.x * blockDim.x + threadIdx.x;
    long stride = (long)gridDim.x * blockDim.x;
    for (; i < n4; i += stride) {
        float4 v = src[i];
        float vv[4] = {v.x, v.y, v.z, v.w};
        __nv_bfloat16 h[4], l[4];
#pragma unroll
        for (int j = 0; j < 4; j++) {
            h[j] = __float2bfloat16(vv[j]);
            l[j] = __float2bfloat16(vv[j] - __bfloat162float(h[j]));
        }
        u64 hp, lp;
        __builtin_memcpy(&hp, h, 8); __builtin_memcpy(&lp, l, 8);
        hi[i] = hp; lo[i] = lp;
    }
}

// gather W_all input part (cols 0..511) + bias into g_WA*, g_ball
__global__ void k_cvt_wall(
    const float* __restrict__ Wf, const float* __restrict__ bf,
    const float* __restrict__ Wi, const float* __restrict__ bi,
    const float* __restrict__ Wo, const float* __restrict__ bo,
    const float* __restrict__ Wg, const float* __restrict__ bg)
{
    int n = blockIdx.x;                 // 0..4095
    int q = n >> 10, j = n & 1023;
    const float* Wq = (q == 0) ? Wf : (q == 1) ? Wi : (q == 2) ? Wo : Wg;
    const float* bq = (q == 0) ? bf : (q == 1) ? bi : (q == 2) ? bo : bg;
    int k = threadIdx.x * 4;            // 128 threads
    float4 v = *(const float4*)(Wq + (size_t)j * CDIM + k);
    float vv[4] = {v.x, v.y, v.z, v.w};
    __nv_bfloat16 h[4], l[4];
#pragma unroll
    for (int t = 0; t < 4; t++) {
        h[t] = __float2bfloat16(vv[t]);
        l[t] = __float2bfloat16(vv[t] - __bfloat162float(h[t]));
    }
    u64 hp, lp;
    __builtin_memcpy(&hp, h, 8); __builtin_memcpy(&lp, l, 8);
    *(u64*)(g_WAhi + (size_t)n * 512 + k) = hp;
    *(u64*)(g_WAlo + (size_t)n * 512 + k) = lp;
    if (threadIdx.x == 0) g_ball[n] = bq[j];
}

// =====================================================================
// k_tgemm: C[M,N] = (Ahi+Alo) @ (Bhi+Blo)^T + bias, split-bf16 mma.sync.
// CTA tile 128x128, 8 warps (4M x 2N), warp tile 32x64, K-chunk 32.
// mode 1: A=X, B=WA, bias=g_ball, epilogue -> g_Gx permuted (pregemm)
// mode 0: A=H, B=Wy, bias=ext,    epilogue -> outp rows (k_out)
// =====================================================================
#define TS 40   // smem row stride in bf16 elems (80 B: 16B-aligned, conflict-free)
__global__ __launch_bounds__(256) void k_tgemm(
    const float* __restrict__ bias_ext, float* __restrict__ outp, int K, int mode)
{
    __shared__ __align__(16) __nv_bfloat16 sm[4][128 * TS];

    const int tid  = threadIdx.x;
    const int lane = tid & 31, w = tid >> 5;
    const int wm = w & 3, wn = w >> 2;
    const int m0 = blockIdx.y * 128, n0 = blockIdx.x * 128;

    const __nv_bfloat16* bases[4];
    const float* bias;
    if (mode == 1) {
        bases[0] = g_Xhi  + (size_t)m0 * K;  bases[1] = g_Xlo  + (size_t)m0 * K;
        bases[2] = g_WAhi + (size_t)n0 * K;  bases[3] = g_WAlo + (size_t)n0 * K;
        bias = g_ball;
    } else {
        bases[0] = g_Hhi  + (size_t)m0 * K;  bases[1] = g_Hlo  + (size_t)m0 * K;
        bases[2] = g_Wyhi + (size_t)n0 * K;  bases[3] = g_Wylo + (size_t)n0 * K;
        bias = bias_ext;
    }

    float acc[2][8][4];
#pragma unroll
    for (int mt = 0; mt < 2; mt++)
#pragma unroll
        for (int nt = 0; nt < 8; nt++)
#pragma unroll
            for (int f = 0; f < 4; f++) acc[mt][nt][f] = 0.0f;

    // ldmatrix per-lane geometry
    const int arow = ((lane >> 3) & 1) * 8 + (lane & 7);   // + mt*16 + wm*32
    const int akof = ((lane >> 4) & 1) * 8;                // + kstep*16
    const int brow = ((lane >> 4) & 1) * 8 + (lane & 7);   // + ntp*16 + wn*64
    const int bkof = ((lane >> 3) & 1) * 8;                // + kstep*16

    // global loader: 8 x uint4 per thread per chunk
    int ld_tile[8], ld_r[8], ld_slot[8];
#pragma unroll
    for (int i = 0; i < 8; i++) {
        int e = tid + i * 256;
        ld_tile[i] = e >> 9; ld_r[i] = (e >> 2) & 127; ld_slot[i] = e & 3;
    }

    const int chunks = K >> 5;
    uint4 pf[8];
#pragma unroll
    for (int i = 0; i < 8; i++)
        pf[i] = *(const uint4*)(bases[ld_tile[i]] + (size_t)ld_r[i] * K + ld_slot[i] * 8);

    for (int ch = 0; ch < chunks; ch++) {
        __syncthreads();
#pragma unroll
        for (int i = 0; i < 8; i++)
            *(uint4*)(&sm[ld_tile[i]][ld_r[i] * TS + ld_slot[i] * 8]) = pf[i];
        __syncthreads();
        if (ch + 1 < chunks) {
            int ko = (ch + 1) * 32;
#pragma unroll
            for (int i = 0; i < 8; i++)
                pf[i] = *(const uint4*)(bases[ld_tile[i]] + (size_t)ld_r[i] * K + ko + ld_slot[i] * 8);
        }

#pragma unroll
        for (int kstep = 0; kstep < 2; kstep++) {
            uint32_t afr[2][2][4];   // [mt][hi/lo][4]
#pragma unroll
            for (int mt = 0; mt < 2; mt++)
#pragma unroll
                for (int s = 0; s < 2; s++) {
                    uint32_t addr = smem_u32(
                        &sm[s][(wm * 32 + mt * 16 + arow) * TS + akof + kstep * 16]);
                    ldmx4(afr[mt][s], addr);
                }
            uint32_t bfr[8][2][2];   // [nt][hi/lo][2]
#pragma unroll
            for (int ntp = 0; ntp < 4; ntp++)
#pragma unroll
                for (int s = 0; s < 2; s++) {
                    uint32_t r4[4];
                    uint32_t addr = smem_u32(
                        &sm[2 + s][(wn * 64 + ntp * 16 + brow) * TS + bkof + kstep * 16]);
                    ldmx4(r4, addr);
                    bfr[ntp * 2][s][0]     = r4[0];
                    bfr[ntp * 2][s][1]     = r4[1];
                    bfr[ntp * 2 + 1][s][0] = r4[2];
                    bfr[ntp * 2 + 1][s][1] = r4[3];
                }
#pragma unroll
            for (int mt = 0; mt < 2; mt++)
#pragma unroll
                for (int nt = 0; nt < 8; nt++) {
                    mma_bf16(acc[mt][nt], afr[mt][0], bfr[nt][0]);  // hi*hi
                    mma_bf16(acc[mt][nt], afr[mt][1], bfr[nt][0]);  // lo*hi
                    mma_bf16(acc[mt][nt], afr[mt][0], bfr[nt][1]);  // hi*lo
                }
        }
    }

    // ---- epilogue ----
    const int mrow = lane >> 2;          // 0..7
    const int ncol = (lane & 3) * 2;     // 0,2,4,6
#pragma unroll
    for (int mt = 0; mt < 2; mt++) {
#pragma unroll
        for (int nt = 0; nt < 8; nt++) {
            int nloc = wn * 64 + nt * 8 + ncol;
            int nglb = n0 + nloc;
            float2 bv = {bias[nglb], bias[nglb + 1]};
#pragma unroll
            for (int half = 0; half < 2; half++) {
                int gm = m0 + wm * 32 + mt * 16 + mrow + half * 8;
                float2 v;
                v.x = acc[mt][nt][half * 2 + 0] + bv.x;
                v.y = acc[mt][nt][half * 2 + 1] + bv.y;
                if (mode == 0) {
                    *(float2*)(outp + (size_t)gm * OUTD + nglb) = v;
                } else {
                    int q  = n0 >> 10;
                    int jj = (n0 & 1023) + nloc;
                    int ntidx = jj >> 3, jl = jj & 7;
                    int tt = gm >> 6, b = gm & 63;
                    *(float2*)(g_Gx + (((size_t)tt * NCTA + ntidx) * 64 + b) * 32
                               + q * 8 + jl) = v;
                }
            }
        }
    }
}

// =====================================================================
// kernel B: PERSISTENT recurrence (verbatim from R5 — passing)
// =====================================================================
__global__ __launch_bounds__(THR, 1) void k_recur(
    const float* __restrict__ Wf, const float* __restrict__ Wi,
    const float* __restrict__ Wo, const float* __restrict__ Wg)
{
    extern __shared__ char smem[];
    u64*   wsk = (u64*)(smem + W_OFF);
    u64*   hsk = (u64*)(smem + H_OFF);
    float* red = (float*)(smem + RED_OFF);
    float* cs  = (float*)(smem + CS_OFF);

    const int tid = threadIdx.x;
    const int n   = blockIdx.x;

#pragma unroll 4
    for (int i = 0; i < 32; i++) {
        int e = tid + i * 512;
        int c = e & 31, k2 = e >> 5;
        int q = c >> 3, j = c & 7;
        const float* Wq = (q == 0) ? Wf : (q == 1) ? Wi : (q == 2) ? Wo : Wg;
        wsk[(size_t)k2 * W_STRIDE + c] =
            *(const u64*)(Wq + (size_t)(n * 8 + j) * CDIM + IND + k2 * 2);
    }
    cs[(tid >> 3) * 9 + (tid & 7)] = 0.0f;
    __syncthreads();

    const int kg  = tid >> 7;
    const int l   = tid & 127;
    const int ww  = (tid >> 5) & 3;
    const int lam = tid & 31;
    const int b0  = (l >> 3) * 4;
    const int c0  = (l & 7) * 4;
    u64* hbuf = hsk + kg * (16 * H_STRIDE);
    const int b_act = tid >> 3, j_act = tid & 7;

    const int lrow0 = ww * 16 + (lam >> 3);
    const int lk2   = (lam & 7) * 2;

    for (int t = 0; t < SEQ; t++) {
        const float* gxp = g_Gx + (((size_t)t * NCTA + n) * 64 + b_act) * 32 + j_act;
        float gx0 = gxp[0], gx1 = gxp[8], gx2 = gxp[16], gx3 = gxp[24];

        if (t > 0) {
            if (tid == 0) {
                int target = NCTA * t, v;
                do {
                    asm volatile("ld.acquire.gpu.global.s32 %0, [%1];"
                                 : "=r"(v) : "l"(&g_done) : "memory");
                } while (v < target);
            }
            __syncthreads();

            const u64* hbase = (const u64*)g_Hall + (size_t)t * 32768 + kg * 128 + lk2;

            u64 acc[4][4];
#pragma unroll
            for (int r = 0; r < 4; r++)
#pragma unroll
                for (int c = 0; c < 4; c++) acc[r][c] = 0ull;

            ulonglong2 pf[4];
#pragma unroll
            for (int i = 0; i < 4; i++)
                pf[i] = *(const ulonglong2*)(hbase + (size_t)(lrow0 + i * 4) * 512);

#pragma unroll 1
            for (int ch = 0; ch < 8; ch++) {
                asm volatile("bar.sync %0, %1;" :: "r"(kg + 1), "r"(128) : "memory");
#pragma unroll
                for (int i = 0; i < 4; i++) {
                    int r = lrow0 + i * 4;
                    hbuf[(lk2 + 0) * H_STRIDE + r] = pf[i].x;
                    hbuf[(lk2 + 1) * H_STRIDE + r] = pf[i].y;
                }
                asm volatile("bar.sync %0, %1;" :: "r"(kg + 1), "r"(128) : "memory");
                if (ch < 7) {
                    const u64* nxt = hbase + (ch + 1) * 16;
#pragma unroll
                    for (int i = 0; i < 4; i++)
                        pf[i] = *(const ulonglong2*)(nxt + (size_t)(lrow0 + i * 4) * 512);
                }
                const u64* wrow = wsk + (size_t)(kg * 128 + ch * 16) * W_STRIDE;
#pragma unroll
                for (int kk2 = 0; kk2 < 16; kk2++) {
                    const u64* hp = hbuf + kk2 * H_STRIDE;
                    const u64* wp = wrow + kk2 * W_STRIDE;
                    ulonglong2 h01 = *(const ulonglong2*)(hp + b0);
                    ulonglong2 h23 = *(const ulonglong2*)(hp + b0 + 2);
                    ulonglong2 wA  = *(const ulonglong2*)(wp + c0);
                    ulonglong2 wB  = *(const ulonglong2*)(wp + c0 + 2);
                    acc[0][0]=fma2(h01.x,wA.x,acc[0][0]); acc[0][1]=fma2(h01.x,wA.y,acc[0][1]);
                    acc[0][2]=fma2(h01.x,wB.x,acc[0][2]); acc[0][3]=fma2(h01.x,wB.y,acc[0][3]);
                    acc[1][0]=fma2(h01.y,wA.x,acc[1][0]); acc[1][1]=fma2(h01.y,wA.y,acc[1][1]);
                    acc[1][2]=fma2(h01.y,wB.x,acc[1][2]); acc[1][3]=fma2(h01.y,wB.y,acc[1][3]);
                    acc[2][0]=fma2(h23.x,wA.x,acc[2][0]); acc[2][1]=fma2(h23.x,wA.y,acc[2][1]);
                    acc[2][2]=fma2(h23.x,wB.x,acc[2][2]); acc[2][3]=fma2(h23.x,wB.y,acc[2][3]);
                    acc[3][0]=fma2(h23.y,wA.x,acc[3][0]); acc[3][1]=fma2(h23.y,wA.y,acc[3][1]);
                    acc[3][2]=fma2(h23.y,wB.x,acc[3][2]); acc[3][3]=fma2(h23.y,wB.y,acc[3][3]);
                }
            }

            float* rb = red + (size_t)kg * (64 * 33);
#pragma unroll
            for (int r = 0; r < 4; r++) {
#pragma unroll
                for (int c = 0; c < 4; c++)
                    rb[(b0 + r) * 33 + c0 + c] = fold(acc[r][c]);
            }
            __syncthreads();
        }

        {
            float fv = gx0, iv = gx1, ov = gx2, gv = gx3;
            if (t > 0) {
                const float* rr = red + b_act * 33 + j_act;
#pragma unroll
                for (int g = 0; g < 4; g++) {
                    fv += rr[g * 2112];
                    iv += rr[g * 2112 + 8];
                    ov += rr[g * 2112 + 16];
                    gv += rr[g * 2112 + 24];
                }
            }
            float f  = sigm(fv), ii = sigm(iv), oo = sigm(ov), gt = tanhf(gv);
            float cprev = cs[b_act * 9 + j_act];
            float cn = f * cprev + ii * gt;
            cs[b_act * 9 + j_act] = cn;
            g_Hall[(size_t)(t + 1) * 65536 + (size_t)b_act * 1024 + n * 8 + j_act]
                = oo * tanhf(cn);
        }

        __syncthreads();
        if (tid == 0)
            asm volatile("red.release.gpu.global.add.s32 [%0], %1;"
                         :: "l"(&g_done), "r"(1) : "memory");
    }
}

// ---------------- launch ----------------
extern "C" void kernel_launch(void* const* d_in, const int* in_sizes, int n_in,
                              void* d_out, int out_size) {
    const float* x  = (const float*)d_in[0];
    const float* Wf = (const float*)d_in[1];
    const float* bf = (const float*)d_in[2];
    const float* Wi = (const float*)d_in[3];
    const float* bi = (const float*)d_in[4];
    const float* Wo = (const float*)d_in[5];
    const float* bo = (const float*)d_in[6];
    const float* Wg = (const float*)d_in[7];
    const float* bg = (const float*)d_in[8];
    const float* Wy = (const float*)d_in[9];
    const float* by = (const float*)d_in[10];
    float* out = (float*)d_out;

    cudaFuncSetAttribute(k_recur, cudaFuncAttributeMaxDynamicSharedMemorySize, SMEM_RECUR);

    k_init<<<1, 32>>>();

    // converts for pregemm
    k_cvt<<<4096, 256>>>((const float4*)x, (long)SEQ * BATCH * IND / 4, 0);
    k_cvt_wall<<<4096, 128>>>(Wf, bf, Wi, bi, Wo, bo, Wg, bg);
    k_cvt<<<512, 256>>>((const float4*)Wy, (long)OUTD * HID / 4, 1);

    // pregemm: Gx = X @ W_all^T + b_all  (M=32768, N=4096, K=512) -> permuted
    k_tgemm<<<dim3(32, 256), 256>>>(nullptr, nullptr, IND, 1);

    // recurrence (fp32, persistent)
    k_recur<<<NCTA, THR, SMEM_RECUR>>>(Wf, Wi, Wo, Wg);

    // convert H, then out = H @ Wy^T + by  (M=32768, N=512, K=1024)
    k_cvt<<<8192, 256>>>(nullptr, (long)SEQ * BATCH * HID / 4, 2);
    k_tgemm<<<dim3(4, 256), 256>>>(by, out, HID, 0);
}

// round 8
// speedup vs baseline: 1.7659x; 1.4578x over previous
#include <cuda_runtime.h>
#include <cuda_bf16.h>
#include <math.h>
#include <stdint.h>

// Problem dims (fixed)
#define SEQ   512
#define BATCH 64
#define IND   512
#define HID   1024
#define OUTD  512
#define CDIM  1536

#define NCTA  128          // recurrence CTAs: CTA n owns cols c=q*8+jl, j=n*8+jl

typedef unsigned long long u64;

// ---- k_recur smem layout (bytes) ----
#define RW_STRIDE 1032     // W smem row stride (bf16 elems)
#define RH_STRIDE 136      // h smem row stride (bf16 elems)
#define R_WHI 0
#define R_WLO 66048
#define R_HHI 132096
#define R_HLO 149504
#define R_GACT 166912      // float[64][34]
#define SMEM_R (166912 + 8704)   // 175616

// ---------------- scratch ----------------
__device__ float g_Gx  [(size_t)SEQ * NCTA * BATCH * 32];   // [t][n][b][c], c=q*8+jl
__device__ int   g_done;
__device__ __nv_bfloat16 g_Xhi [(size_t)SEQ * BATCH * IND];
__device__ __nv_bfloat16 g_Xlo [(size_t)SEQ * BATCH * IND];
__device__ __nv_bfloat16 g_WAhi[(size_t)4096 * 512];
__device__ __nv_bfloat16 g_WAlo[(size_t)4096 * 512];
__device__ __nv_bfloat16 g_Hhi [(size_t)SEQ * BATCH * HID]; // h_{t+1} at rows t*64+b
__device__ __nv_bfloat16 g_Hlo [(size_t)SEQ * BATCH * HID];
__device__ __nv_bfloat16 g_Wyhi[(size_t)OUTD * HID];
__device__ __nv_bfloat16 g_Wylo[(size_t)OUTD * HID];
__device__ float g_ball[4096];

static __device__ __forceinline__ float sigm(float x) { return 1.0f / (1.0f + __expf(-x)); }

// ---------------- mma.sync helpers (proven in R7) ----------------
static __device__ __forceinline__ uint32_t smem_u32(const void* p) {
    uint32_t a;
    asm("{ .reg .u64 t; cvta.to.shared.u64 t, %1; cvt.u32.u64 %0, t; }" : "=r"(a) : "l"(p));
    return a;
}
static __device__ __forceinline__ void ldmx4(uint32_t* r, uint32_t addr) {
    asm volatile("ldmatrix.sync.aligned.m8n8.x4.shared.b16 {%0,%1,%2,%3}, [%4];"
                 : "=r"(r[0]), "=r"(r[1]), "=r"(r[2]), "=r"(r[3]) : "r"(addr));
}
static __device__ __forceinline__ void mma_bf16(float* c, const uint32_t* a, const uint32_t* b) {
    asm volatile(
        "mma.sync.aligned.m16n8k16.row.col.f32.bf16.bf16.f32 "
        "{%0,%1,%2,%3}, {%4,%5,%6,%7}, {%8,%9}, {%0,%1,%2,%3};"
        : "+f"(c[0]), "+f"(c[1]), "+f"(c[2]), "+f"(c[3])
        : "r"(a[0]), "r"(a[1]), "r"(a[2]), "r"(a[3]), "r"(b[0]), "r"(b[1]));
}

__global__ void k_init() { if (threadIdx.x == 0) g_done = 0; }

// =====================================================================
// converters: fp32 -> (bf16 hi, bf16 lo). which: 0=X, 1=Wy
// =====================================================================
__global__ void k_cvt(const float4* __restrict__ src, long n4, int which)
{
    u64 *hi, *lo;
    if (which == 0) { hi = (u64*)g_Xhi;  lo = (u64*)g_Xlo;  }
    else            { hi = (u64*)g_Wyhi; lo = (u64*)g_Wylo; }
    long i = (long)blockIdx.x * blockDim.x + threadIdx.x;
    long stride = (long)gridDim.x * blockDim.x;
    for (; i < n4; i += stride) {
        float4 v = src[i];
        float vv[4] = {v.x, v.y, v.z, v.w};
        __nv_bfloat16 h[4], l[4];
#pragma unroll
        for (int j = 0; j < 4; j++) {
            h[j] = __float2bfloat16(vv[j]);
            l[j] = __float2bfloat16(vv[j] - __bfloat162float(h[j]));
        }
        u64 hp, lp;
        __builtin_memcpy(&hp, h, 8); __builtin_memcpy(&lp, l, 8);
        hi[i] = hp; lo[i] = lp;
    }
}

// gather W_all input part (cols 0..511) + bias into g_WA*, g_ball
__global__ void k_cvt_wall(
    const float* __restrict__ Wf, const float* __restrict__ bf,
    const float* __restrict__ Wi, const float* __restrict__ bi,
    const float* __restrict__ Wo, const float* __restrict__ bo,
    const float* __restrict__ Wg, const float* __restrict__ bg)
{
    int n = blockIdx.x;                 // 0..4095
    int q = n >> 10, j = n & 1023;
    const float* Wq = (q == 0) ? Wf : (q == 1) ? Wi : (q == 2) ? Wo : Wg;
    const float* bq = (q == 0) ? bf : (q == 1) ? bi : (q == 2) ? bo : bg;
    int k = threadIdx.x * 4;
    float4 v = *(const float4*)(Wq + (size_t)j * CDIM + k);
    float vv[4] = {v.x, v.y, v.z, v.w};
    __nv_bfloat16 h[4], l[4];
#pragma unroll
    for (int t = 0; t < 4; t++) {
        h[t] = __float2bfloat16(vv[t]);
        l[t] = __float2bfloat16(vv[t] - __bfloat162float(h[t]));
    }
    u64 hp, lp;
    __builtin_memcpy(&hp, h, 8); __builtin_memcpy(&lp, l, 8);
    *(u64*)(g_WAhi + (size_t)n * 512 + k) = hp;
    *(u64*)(g_WAlo + (size_t)n * 512 + k) = lp;
    if (threadIdx.x == 0) g_ball[n] = bq[j];
}

// =====================================================================
// k_tgemm (verbatim from R7 — passing): split-bf16 mma.sync GEMM
// =====================================================================
#define TS 40
__global__ __launch_bounds__(256) void k_tgemm(
    const float* __restrict__ bias_ext, float* __restrict__ outp, int K, int mode)
{
    __shared__ __align__(16) __nv_bfloat16 sm[4][128 * TS];

    const int tid  = threadIdx.x;
    const int lane = tid & 31, w = tid >> 5;
    const int wm = w & 3, wn = w >> 2;
    const int m0 = blockIdx.y * 128, n0 = blockIdx.x * 128;

    const __nv_bfloat16* bases[4];
    const float* bias;
    if (mode == 1) {
        bases[0] = g_Xhi  + (size_t)m0 * K;  bases[1] = g_Xlo  + (size_t)m0 * K;
        bases[2] = g_WAhi + (size_t)n0 * K;  bases[3] = g_WAlo + (size_t)n0 * K;
        bias = g_ball;
    } else {
        bases[0] = g_Hhi  + (size_t)m0 * K;  bases[1] = g_Hlo  + (size_t)m0 * K;
        bases[2] = g_Wyhi + (size_t)n0 * K;  bases[3] = g_Wylo + (size_t)n0 * K;
        bias = bias_ext;
    }

    float acc[2][8][4];
#pragma unroll
    for (int mt = 0; mt < 2; mt++)
#pragma unroll
        for (int nt = 0; nt < 8; nt++)
#pragma unroll
            for (int f = 0; f < 4; f++) acc[mt][nt][f] = 0.0f;

    const int arow = ((lane >> 3) & 1) * 8 + (lane & 7);
    const int akof = ((lane >> 4) & 1) * 8;
    const int brow = ((lane >> 4) & 1) * 8 + (lane & 7);
    const int bkof = ((lane >> 3) & 1) * 8;

    int ld_tile[8], ld_r[8], ld_slot[8];
#pragma unroll
    for (int i = 0; i < 8; i++) {
        int e = tid + i * 256;
        ld_tile[i] = e >> 9; ld_r[i] = (e >> 2) & 127; ld_slot[i] = e & 3;
    }

    const int chunks = K >> 5;
    uint4 pf[8];
#pragma unroll
    for (int i = 0; i < 8; i++)
        pf[i] = *(const uint4*)(bases[ld_tile[i]] + (size_t)ld_r[i] * K + ld_slot[i] * 8);

    for (int ch = 0; ch < chunks; ch++) {
        __syncthreads();
#pragma unroll
        for (int i = 0; i < 8; i++)
            *(uint4*)(&sm[ld_tile[i]][ld_r[i] * TS + ld_slot[i] * 8]) = pf[i];
        __syncthreads();
        if (ch + 1 < chunks) {
            int ko = (ch + 1) * 32;
#pragma unroll
            for (int i = 0; i < 8; i++)
                pf[i] = *(const uint4*)(bases[ld_tile[i]] + (size_t)ld_r[i] * K + ko + ld_slot[i] * 8);
        }

#pragma unroll
        for (int kstep = 0; kstep < 2; kstep++) {
            uint32_t afr[2][2][4];
#pragma unroll
            for (int mt = 0; mt < 2; mt++)
#pragma unroll
                for (int s = 0; s < 2; s++) {
                    uint32_t addr = smem_u32(
                        &sm[s][(wm * 32 + mt * 16 + arow) * TS + akof + kstep * 16]);
                    ldmx4(afr[mt][s], addr);
                }
            uint32_t bfr[8][2][2];
#pragma unroll
            for (int ntp = 0; ntp < 4; ntp++)
#pragma unroll
                for (int s = 0; s < 2; s++) {
                    uint32_t r4[4];
                    uint32_t addr = smem_u32(
                        &sm[2 + s][(wn * 64 + ntp * 16 + brow) * TS + bkof + kstep * 16]);
                    ldmx4(r4, addr);
                    bfr[ntp * 2][s][0]     = r4[0];
                    bfr[ntp * 2][s][1]     = r4[1];
                    bfr[ntp * 2 + 1][s][0] = r4[2];
                    bfr[ntp * 2 + 1][s][1] = r4[3];
                }
#pragma unroll
            for (int mt = 0; mt < 2; mt++)
#pragma unroll
                for (int nt = 0; nt < 8; nt++) {
                    mma_bf16(acc[mt][nt], afr[mt][0], bfr[nt][0]);
                    mma_bf16(acc[mt][nt], afr[mt][1], bfr[nt][0]);
                    mma_bf16(acc[mt][nt], afr[mt][0], bfr[nt][1]);
                }
        }
    }

    const int mrow = lane >> 2;
    const int ncol = (lane & 3) * 2;
#pragma unroll
    for (int mt = 0; mt < 2; mt++) {
#pragma unroll
        for (int nt = 0; nt < 8; nt++) {
            int nloc = wn * 64 + nt * 8 + ncol;
            int nglb = n0 + nloc;
            float2 bv = {bias[nglb], bias[nglb + 1]};
#pragma unroll
            for (int half = 0; half < 2; half++) {
                int gm = m0 + wm * 32 + mt * 16 + mrow + half * 8;
                float2 v;
                v.x = acc[mt][nt][half * 2 + 0] + bv.x;
                v.y = acc[mt][nt][half * 2 + 1] + bv.y;
                if (mode == 0) {
                    *(float2*)(outp + (size_t)gm * OUTD + nglb) = v;
                } else {
                    int q  = n0 >> 10;
                    int jj = (n0 & 1023) + nloc;
                    int ntidx = jj >> 3, jl = jj & 7;
                    int tt = gm >> 6, b = gm & 63;
                    *(float2*)(g_Gx + (((size_t)tt * NCTA + ntidx) * 64 + b) * 32
                               + q * 8 + jl) = v;
                }
            }
        }
    }
}

// =====================================================================
// k_recur: PERSISTENT recurrence, tensor-core GEMM (split-bf16 mma.sync).
// 128 CTAs x 256 thr (8 warps: 4m x 2n; warp tile 16b x 16c, full K).
// Wh slice resident in smem (bf16 hi/lo); h streamed bf16 hi/lo;
// c-state in registers; one acquire/release sync per step.
// =====================================================================
__global__ __launch_bounds__(256, 1) void k_recur(
    const float* __restrict__ Wf, const float* __restrict__ Wi,
    const float* __restrict__ Wo, const float* __restrict__ Wg)
{
    extern __shared__ char smem[];
    __nv_bfloat16* whi = (__nv_bfloat16*)(smem + R_WHI);   // [32 c][1024 k] stride 1032
    __nv_bfloat16* wlo = (__nv_bfloat16*)(smem + R_WLO);
    __nv_bfloat16* hhi = (__nv_bfloat16*)(smem + R_HHI);   // [64 b][128 k] stride 136
    __nv_bfloat16* hlo = (__nv_bfloat16*)(smem + R_HLO);
    float*         gact = (float*)(smem + R_GACT);          // [64 b][34]

    const int tid = threadIdx.x;
    const int n   = blockIdx.x;

    // ---- one-time: convert W slice to bf16 hi/lo in smem ----
#pragma unroll 4
    for (int i = 0; i < 32; i++) {
        int e = tid + i * 256;              // 0..8191, 4 elems each
        int row = e >> 8;                   // 0..31  (c = q*8+jl)
        int kp  = (e & 255) * 4;
        int q = row >> 3, jl = row & 7;
        const float* Wq = (q == 0) ? Wf : (q == 1) ? Wi : (q == 2) ? Wo : Wg;
        float4 v = *(const float4*)(Wq + (size_t)(n * 8 + jl) * CDIM + IND + kp);
        float vv[4] = {v.x, v.y, v.z, v.w};
        __nv_bfloat16 h4[4], l4[4];
#pragma unroll
        for (int u = 0; u < 4; u++) {
            h4[u] = __float2bfloat16(vv[u]);
            l4[u] = __float2bfloat16(vv[u] - __bfloat162float(h4[u]));
        }
        u64 hp, lp;
        __builtin_memcpy(&hp, h4, 8); __builtin_memcpy(&lp, l4, 8);
        *(u64*)(whi + (size_t)row * RW_STRIDE + kp) = hp;
        *(u64*)(wlo + (size_t)row * RW_STRIDE + kp) = lp;
    }
    __syncthreads();

    const int lane = tid & 31, w = tid >> 5;
    const int wm = w & 3, wn = w >> 2;                      // 4m x 2n warps
    const int arow = ((lane >> 3) & 1) * 8 + (lane & 7);
    const int akof = ((lane >> 4) & 1) * 8;
    const int brow = ((lane >> 4) & 1) * 8 + (lane & 7);
    const int bkof = ((lane >> 3) & 1) * 8;
    const int mrow = lane >> 2;
    const int ncol = (lane & 3) * 2;

    // h-chunk loader geometry (4 uint4 per buffer per thread)
    int lr[4], ls[4];
#pragma unroll
    for (int i = 0; i < 4; i++) {
        int e = tid + i * 256;              // 0..1023
        lr[i] = e >> 4; ls[i] = (e & 15) * 8;
    }

    // activation pairs: thread owns (b,jl) p0 = tid, p1 = tid+256; c in regs
    const int b0a = tid >> 3,          jl0 = tid & 7;
    const int b1a = (tid + 256) >> 3,  jl1 = tid & 7;
    float c0 = 0.0f, c1 = 0.0f;

    for (int t = 0; t < SEQ; t++) {
        // Gx prefetch (independent of h)
        const float* gxb = g_Gx + (((size_t)t * NCTA + n) * 64) * 32;
        float gxA[4], gxB[4];
#pragma unroll
        for (int q = 0; q < 4; q++) {
            gxA[q] = gxb[b0a * 32 + q * 8 + jl0];
            gxB[q] = gxb[b1a * 32 + q * 8 + jl1];
        }

        if (t > 0) {
            if (tid == 0) {
                int target = NCTA * t, v;
                do {
                    asm volatile("ld.acquire.gpu.global.s32 %0, [%1];"
                                 : "=r"(v) : "l"(&g_done) : "memory");
                } while (v < target);
            }
            __syncthreads();

            const __nv_bfloat16* Ghi = g_Hhi + (size_t)(t - 1) * 65536;
            const __nv_bfloat16* Glo = g_Hlo + (size_t)(t - 1) * 65536;

            float acc[2][4];
#pragma unroll
            for (int nt = 0; nt < 2; nt++)
#pragma unroll
                for (int f = 0; f < 4; f++) acc[nt][f] = 0.0f;

            uint4 pfh[4], pfl[4];
#pragma unroll
            for (int i = 0; i < 4; i++) {
                pfh[i] = *(const uint4*)(Ghi + (size_t)lr[i] * 1024 + ls[i]);
                pfl[i] = *(const uint4*)(Glo + (size_t)lr[i] * 1024 + ls[i]);
            }

#pragma unroll 1
            for (int ch = 0; ch < 8; ch++) {
                __syncthreads();
#pragma unroll
                for (int i = 0; i < 4; i++) {
                    *(uint4*)(hhi + (size_t)lr[i] * RH_STRIDE + ls[i]) = pfh[i];
                    *(uint4*)(hlo + (size_t)lr[i] * RH_STRIDE + ls[i]) = pfl[i];
                }
                __syncthreads();
                if (ch < 7) {
                    int ko = (ch + 1) * 128;
#pragma unroll
                    for (int i = 0; i < 4; i++) {
                        pfh[i] = *(const uint4*)(Ghi + (size_t)lr[i] * 1024 + ko + ls[i]);
                        pfl[i] = *(const uint4*)(Glo + (size_t)lr[i] * 1024 + ko + ls[i]);
                    }
                }
#pragma unroll
                for (int kstep = 0; kstep < 8; kstep++) {
                    uint32_t ah[4], al[4];
                    ldmx4(ah, smem_u32(hhi + (size_t)(wm * 16 + arow) * RH_STRIDE
                                        + kstep * 16 + akof));
                    ldmx4(al, smem_u32(hlo + (size_t)(wm * 16 + arow) * RH_STRIDE
                                        + kstep * 16 + akof));
                    uint32_t bh4[4], bl4[4];
                    int wk = ch * 128 + kstep * 16 + bkof;
                    ldmx4(bh4, smem_u32(whi + (size_t)(wn * 16 + brow) * RW_STRIDE + wk));
                    ldmx4(bl4, smem_u32(wlo + (size_t)(wn * 16 + brow) * RW_STRIDE + wk));
                    mma_bf16(acc[0], ah, bh4);
                    mma_bf16(acc[0], al, bh4);
                    mma_bf16(acc[0], ah, bl4);
                    mma_bf16(acc[1], ah, bh4 + 2);
                    mma_bf16(acc[1], al, bh4 + 2);
                    mma_bf16(acc[1], ah, bl4 + 2);
                }
            }

            // write gate pre-activations to gact[b][c]
#pragma unroll
            for (int nt = 0; nt < 2; nt++) {
                int col = wn * 16 + nt * 8 + ncol;
                int r0 = wm * 16 + mrow;
                *(float2*)(gact + (size_t)r0 * 34 + col)       = *(float2*)&acc[nt][0];
                *(float2*)(gact + (size_t)(r0 + 8) * 34 + col) = *(float2*)&acc[nt][2];
            }
            __syncthreads();
        }

        // ---- fused activations + cell update + h write (2 pairs/thread) ----
        {
            float fv = gxA[0], iv = gxA[1], ov = gxA[2], gv = gxA[3];
            if (t > 0) {
                fv += gact[b0a * 34 + jl0];
                iv += gact[b0a * 34 + 8 + jl0];
                ov += gact[b0a * 34 + 16 + jl0];
                gv += gact[b0a * 34 + 24 + jl0];
            }
            float f = sigm(fv), ii = sigm(iv), oo = sigm(ov), gt = tanhf(gv);
            c0 = f * c0 + ii * gt;
            float hv = oo * tanhf(c0);
            __nv_bfloat16 hh = __float2bfloat16(hv);
            size_t idx = ((size_t)t * 64 + b0a) * 1024 + n * 8 + jl0;
            g_Hhi[idx] = hh;
            g_Hlo[idx] = __float2bfloat16(hv - __bfloat162float(hh));
        }
        {
            float fv = gxB[0], iv = gxB[1], ov = gxB[2], gv = gxB[3];
            if (t > 0) {
                fv += gact[b1a * 34 + jl1];
                iv += gact[b1a * 34 + 8 + jl1];
                ov += gact[b1a * 34 + 16 + jl1];
                gv += gact[b1a * 34 + 24 + jl1];
            }
            float f = sigm(fv), ii = sigm(iv), oo = sigm(ov), gt = tanhf(gv);
            c1 = f * c1 + ii * gt;
            float hv = oo * tanhf(c1);
            __nv_bfloat16 hh = __float2bfloat16(hv);
            size_t idx = ((size_t)t * 64 + b1a) * 1024 + n * 8 + jl1;
            g_Hhi[idx] = hh;
            g_Hlo[idx] = __float2bfloat16(hv - __bfloat162float(hh));
        }

        __syncthreads();
        if (tid == 0)
            asm volatile("red.release.gpu.global.add.s32 [%0], %1;"
                         :: "l"(&g_done), "r"(1) : "memory");
    }
}

// ---------------- launch ----------------
extern "C" void kernel_launch(void* const* d_in, const int* in_sizes, int n_in,
                              void* d_out, int out_size) {
    const float* x  = (const float*)d_in[0];
    const float* Wf = (const float*)d_in[1];
    const float* bf = (const float*)d_in[2];
    const float* Wi = (const float*)d_in[3];
    const float* bi = (const float*)d_in[4];
    const float* Wo = (const float*)d_in[5];
    const float* bo = (const float*)d_in[6];
    const float* Wg = (const float*)d_in[7];
    const float* bg = (const float*)d_in[8];
    const float* Wy = (const float*)d_in[9];
    const float* by = (const float*)d_in[10];
    float* out = (float*)d_out;

    cudaFuncSetAttribute(k_recur, cudaFuncAttributeMaxDynamicSharedMemorySize, SMEM_R);

    k_init<<<1, 32>>>();

    // converts for the bulk GEMMs
    k_cvt<<<4096, 256>>>((const float4*)x, (long)SEQ * BATCH * IND / 4, 0);
    k_cvt_wall<<<4096, 128>>>(Wf, bf, Wi, bi, Wo, bo, Wg, bg);
    k_cvt<<<512, 256>>>((const float4*)Wy, (long)OUTD * HID / 4, 1);

    // pregemm: Gx = X @ W_all^T + b_all -> permuted [t][n][b][c]
    k_tgemm<<<dim3(32, 256), 256>>>(nullptr, nullptr, IND, 1);

    // recurrence (tensor-core, persistent)
    k_recur<<<NCTA, 256, SMEM_R>>>(Wf, Wi, Wo, Wg);

    // out = H @ Wy^T + by  (A = g_Hhi/g_Hlo written by k_recur)
    k_tgemm<<<dim3(4, 256), 256>>>(by, out, HID, 0);
}

// round 9
// speedup vs baseline: 2.7621x; 1.5641x over previous
#include <cuda_runtime.h>
#include <cuda_bf16.h>
#include <math.h>
#include <stdint.h>

// Problem dims (fixed)
#define SEQ   512
#define BATCH 64
#define IND   512
#define HID   1024
#define OUTD  512
#define CDIM  1536

#define NCTA  128          // recurrence CTAs: CTA n owns cols c=q*8+jl, j=n*8+jl

typedef unsigned long long u64;

// ---- k_recur smem layout (bytes) ----
#define RW_STRIDE 1032     // W smem row stride (bf16 elems)
#define RH        136      // h smem row stride (bf16 elems)
#define R_WHI 0                       // 32 x 1032 x2B        = 66048
#define R_WLO 66048                   //                      -> 132096
#define R_HB  132096                  // 2 bufs x (hi+lo) x 64x136x2B = 4x17408 -> 201728
#define HBUF_SZ 34816                 // one buf: hi(17408) + lo(17408)
#define R_GACT 201728                 // float[2][64*34] = 2x8704 -> 219136
#define SMEM_R 219136

// ---------------- scratch ----------------
__device__ float g_Gx  [(size_t)SEQ * NCTA * BATCH * 32];   // [t][n][b][c], c=q*8+jl
__device__ int   g_done;
__device__ __nv_bfloat16 g_Xhi [(size_t)SEQ * BATCH * IND];
__device__ __nv_bfloat16 g_Xlo [(size_t)SEQ * BATCH * IND];
__device__ __nv_bfloat16 g_WAhi[(size_t)4096 * 512];
__device__ __nv_bfloat16 g_WAlo[(size_t)4096 * 512];
__device__ __nv_bfloat16 g_Hhi [(size_t)SEQ * BATCH * HID]; // h for step t at rows t*64+b
__device__ __nv_bfloat16 g_Hlo [(size_t)SEQ * BATCH * HID];
__device__ __nv_bfloat16 g_Wyhi[(size_t)OUTD * HID];
__device__ __nv_bfloat16 g_Wylo[(size_t)OUTD * HID];
__device__ float g_ball[4096];

static __device__ __forceinline__ float sigm(float x) { return 1.0f / (1.0f + __expf(-x)); }

// ---------------- mma.sync helpers (proven R7/R8) ----------------
static __device__ __forceinline__ uint32_t smem_u32(const void* p) {
    uint32_t a;
    asm("{ .reg .u64 t; cvta.to.shared.u64 t, %1; cvt.u32.u64 %0, t; }" : "=r"(a) : "l"(p));
    return a;
}
static __device__ __forceinline__ void ldmx4(uint32_t* r, uint32_t addr) {
    asm volatile("ldmatrix.sync.aligned.m8n8.x4.shared.b16 {%0,%1,%2,%3}, [%4];"
                 : "=r"(r[0]), "=r"(r[1]), "=r"(r[2]), "=r"(r[3]) : "r"(addr));
}
static __device__ __forceinline__ void mma_bf16(float* c, const uint32_t* a, const uint32_t* b) {
    asm volatile(
        "mma.sync.aligned.m16n8k16.row.col.f32.bf16.bf16.f32 "
        "{%0,%1,%2,%3}, {%4,%5,%6,%7}, {%8,%9}, {%0,%1,%2,%3};"
        : "+f"(c[0]), "+f"(c[1]), "+f"(c[2]), "+f"(c[3])
        : "r"(a[0]), "r"(a[1]), "r"(a[2]), "r"(a[3]), "r"(b[0]), "r"(b[1]));
}

__global__ void k_init() { if (threadIdx.x == 0) g_done = 0; }

// =====================================================================
// converters: fp32 -> (bf16 hi, bf16 lo). which: 0=X, 1=Wy
// =====================================================================
__global__ void k_cvt(const float4* __restrict__ src, long n4, int which)
{
    u64 *hi, *lo;
    if (which == 0) { hi = (u64*)g_Xhi;  lo = (u64*)g_Xlo;  }
    else            { hi = (u64*)g_Wyhi; lo = (u64*)g_Wylo; }
    long i = (long)blockIdx.x * blockDim.x + threadIdx.x;
    long stride = (long)gridDim.x * blockDim.x;
    for (; i < n4; i += stride) {
        float4 v = src[i];
        float vv[4] = {v.x, v.y, v.z, v.w};
        __nv_bfloat16 h[4], l[4];
#pragma unroll
        for (int j = 0; j < 4; j++) {
            h[j] = __float2bfloat16(vv[j]);
            l[j] = __float2bfloat16(vv[j] - __bfloat162float(h[j]));
        }
        u64 hp, lp;
        __builtin_memcpy(&hp, h, 8); __builtin_memcpy(&lp, l, 8);
        hi[i] = hp; lo[i] = lp;
    }
}

// gather W_all input part (cols 0..511) + bias into g_WA*, g_ball
__global__ void k_cvt_wall(
    const float* __restrict__ Wf, const float* __restrict__ bf,
    const float* __restrict__ Wi, const float* __restrict__ bi,
    const float* __restrict__ Wo, const float* __restrict__ bo,
    const float* __restrict__ Wg, const float* __restrict__ bg)
{
    int n = blockIdx.x;                 // 0..4095
    int q = n >> 10, j = n & 1023;
    const float* Wq = (q == 0) ? Wf : (q == 1) ? Wi : (q == 2) ? Wo : Wg;
    const float* bq = (q == 0) ? bf : (q == 1) ? bi : (q == 2) ? bo : bg;
    int k = threadIdx.x * 4;
    float4 v = *(const float4*)(Wq + (size_t)j * CDIM + k);
    float vv[4] = {v.x, v.y, v.z, v.w};
    __nv_bfloat16 h[4], l[4];
#pragma unroll
    for (int t = 0; t < 4; t++) {
        h[t] = __float2bfloat16(vv[t]);
        l[t] = __float2bfloat16(vv[t] - __bfloat162float(h[t]));
    }
    u64 hp, lp;
    __builtin_memcpy(&hp, h, 8); __builtin_memcpy(&lp, l, 8);
    *(u64*)(g_WAhi + (size_t)n * 512 + k) = hp;
    *(u64*)(g_WAlo + (size_t)n * 512 + k) = lp;
    if (threadIdx.x == 0) g_ball[n] = bq[j];
}

// =====================================================================
// k_tgemm (verbatim from R7/R8 — passing): split-bf16 mma.sync GEMM
// =====================================================================
#define TS 40
__global__ __launch_bounds__(256) void k_tgemm(
    const float* __restrict__ bias_ext, float* __restrict__ outp, int K, int mode)
{
    __shared__ __align__(16) __nv_bfloat16 sm[4][128 * TS];

    const int tid  = threadIdx.x;
    const int lane = tid & 31, w = tid >> 5;
    const int wm = w & 3, wn = w >> 2;
    const int m0 = blockIdx.y * 128, n0 = blockIdx.x * 128;

    const __nv_bfloat16* bases[4];
    const float* bias;
    if (mode == 1) {
        bases[0] = g_Xhi  + (size_t)m0 * K;  bases[1] = g_Xlo  + (size_t)m0 * K;
        bases[2] = g_WAhi + (size_t)n0 * K;  bases[3] = g_WAlo + (size_t)n0 * K;
        bias = g_ball;
    } else {
        bases[0] = g_Hhi  + (size_t)m0 * K;  bases[1] = g_Hlo  + (size_t)m0 * K;
        bases[2] = g_Wyhi + (size_t)n0 * K;  bases[3] = g_Wylo + (size_t)n0 * K;
        bias = bias_ext;
    }

    float acc[2][8][4];
#pragma unroll
    for (int mt = 0; mt < 2; mt++)
#pragma unroll
        for (int nt = 0; nt < 8; nt++)
#pragma unroll
            for (int f = 0; f < 4; f++) acc[mt][nt][f] = 0.0f;

    const int arow = ((lane >> 3) & 1) * 8 + (lane & 7);
    const int akof = ((lane >> 4) & 1) * 8;
    const int brow = ((lane >> 4) & 1) * 8 + (lane & 7);
    const int bkof = ((lane >> 3) & 1) * 8;

    int ld_tile[8], ld_r[8], ld_slot[8];
#pragma unroll
    for (int i = 0; i < 8; i++) {
        int e = tid + i * 256;
        ld_tile[i] = e >> 9; ld_r[i] = (e >> 2) & 127; ld_slot[i] = e & 3;
    }

    const int chunks = K >> 5;
    uint4 pf[8];
#pragma unroll
    for (int i = 0; i < 8; i++)
        pf[i] = *(const uint4*)(bases[ld_tile[i]] + (size_t)ld_r[i] * K + ld_slot[i] * 8);

    for (int ch = 0; ch < chunks; ch++) {
        __syncthreads();
#pragma unroll
        for (int i = 0; i < 8; i++)
            *(uint4*)(&sm[ld_tile[i]][ld_r[i] * TS + ld_slot[i] * 8]) = pf[i];
        __syncthreads();
        if (ch + 1 < chunks) {
            int ko = (ch + 1) * 32;
#pragma unroll
            for (int i = 0; i < 8; i++)
                pf[i] = *(const uint4*)(bases[ld_tile[i]] + (size_t)ld_r[i] * K + ko + ld_slot[i] * 8);
        }

#pragma unroll
        for (int kstep = 0; kstep < 2; kstep++) {
            uint32_t afr[2][2][4];
#pragma unroll
            for (int mt = 0; mt < 2; mt++)
#pragma unroll
                for (int s = 0; s < 2; s++) {
                    uint32_t addr = smem_u32(
                        &sm[s][(wm * 32 + mt * 16 + arow) * TS + akof + kstep * 16]);
                    ldmx4(afr[mt][s], addr);
                }
            uint32_t bfr[8][2][2];
#pragma unroll
            for (int ntp = 0; ntp < 4; ntp++)
#pragma unroll
                for (int s = 0; s < 2; s++) {
                    uint32_t r4[4];
                    uint32_t addr = smem_u32(
                        &sm[2 + s][(wn * 64 + ntp * 16 + brow) * TS + bkof + kstep * 16]);
                    ldmx4(r4, addr);
                    bfr[ntp * 2][s][0]     = r4[0];
                    bfr[ntp * 2][s][1]     = r4[1];
                    bfr[ntp * 2 + 1][s][0] = r4[2];
                    bfr[ntp * 2 + 1][s][1] = r4[3];
                }
#pragma unroll
            for (int mt = 0; mt < 2; mt++)
#pragma unroll
                for (int nt = 0; nt < 8; nt++) {
                    mma_bf16(acc[mt][nt], afr[mt][0], bfr[nt][0]);
                    mma_bf16(acc[mt][nt], afr[mt][1], bfr[nt][0]);
                    mma_bf16(acc[mt][nt], afr[mt][0], bfr[nt][1]);
                }
        }
    }

    const int mrow = lane >> 2;
    const int ncol = (lane & 3) * 2;
#pragma unroll
    for (int mt = 0; mt < 2; mt++) {
#pragma unroll
        for (int nt = 0; nt < 8; nt++) {
            int nloc = wn * 64 + nt * 8 + ncol;
            int nglb = n0 + nloc;
            float2 bv = {bias[nglb], bias[nglb + 1]};
#pragma unroll
            for (int half = 0; half < 2; half++) {
                int gm = m0 + wm * 32 + mt * 16 + mrow + half * 8;
                float2 v;
                v.x = acc[mt][nt][half * 2 + 0] + bv.x;
                v.y = acc[mt][nt][half * 2 + 1] + bv.y;
                if (mode == 0) {
                    *(float2*)(outp + (size_t)gm * OUTD + nglb) = v;
                } else {
                    int q  = n0 >> 10;
                    int jj = (n0 & 1023) + nloc;
                    int ntidx = jj >> 3, jl = jj & 7;
                    int tt = gm >> 6, b = gm & 63;
                    *(float2*)(g_Gx + (((size_t)tt * NCTA + ntidx) * 64 + b) * 32
                               + q * 8 + jl) = v;
                }
            }
        }
    }
}

// =====================================================================
// k_recur: PERSISTENT recurrence, split-bf16 mma.sync.
// 128 CTAs x 512 thr (16 warps: 4m x 2n x 2kg; warp tile 16b x 16c,
// kg interleaves ksteps within each chunk). Double-buffered h smem.
// W resident bf16 hi/lo in smem; c-state in regs; 1 global sync/step.
// =====================================================================
__global__ __launch_bounds__(512, 1) void k_recur(
    const float* __restrict__ Wf, const float* __restrict__ Wi,
    const float* __restrict__ Wo, const float* __restrict__ Wg)
{
    extern __shared__ char smem[];
    __nv_bfloat16* whi = (__nv_bfloat16*)(smem + R_WHI);   // [32 c][1024 k] stride 1032
    __nv_bfloat16* wlo = (__nv_bfloat16*)(smem + R_WLO);
    float*         gact = (float*)(smem + R_GACT);          // [2 kg][64 b][34]

    const int tid = threadIdx.x;
    const int n   = blockIdx.x;

    // ---- one-time: convert W slice to bf16 hi/lo in smem ----
#pragma unroll 4
    for (int i = 0; i < 16; i++) {
        int e = tid + i * 512;              // 0..8191, float4 each
        int row = e >> 8;                   // 0..31  (c = q*8+jl)
        int kp  = (e & 255) * 4;
        int q = row >> 3, jl = row & 7;
        const float* Wq = (q == 0) ? Wf : (q == 1) ? Wi : (q == 2) ? Wo : Wg;
        float4 v = *(const float4*)(Wq + (size_t)(n * 8 + jl) * CDIM + IND + kp);
        float vv[4] = {v.x, v.y, v.z, v.w};
        __nv_bfloat16 h4[4], l4[4];
#pragma unroll
        for (int u = 0; u < 4; u++) {
            h4[u] = __float2bfloat16(vv[u]);
            l4[u] = __float2bfloat16(vv[u] - __bfloat162float(h4[u]));
        }
        u64 hp, lp;
        __builtin_memcpy(&hp, h4, 8); __builtin_memcpy(&lp, l4, 8);
        *(u64*)(whi + (size_t)row * RW_STRIDE + kp) = hp;
        *(u64*)(wlo + (size_t)row * RW_STRIDE + kp) = lp;
    }
    __syncthreads();

    const int lane = tid & 31, wid = tid >> 5;
    const int kg = wid & 1;                 // k-interleave half
    const int wn = (wid >> 1) & 1;          // 2 n-tiles
    const int wm = wid >> 2;                // 4 m-tiles
    const int arow = ((lane >> 3) & 1) * 8 + (lane & 7);
    const int akof = ((lane >> 4) & 1) * 8;
    const int brow = ((lane >> 4) & 1) * 8 + (lane & 7);
    const int bkof = ((lane >> 3) & 1) * 8;
    const int mrow = lane >> 2;
    const int ncol = (lane & 3) * 2;

    // h-chunk loader geometry: 2 uint4 per hi + 2 per lo per thread
    int lr[2], lsl[2];
#pragma unroll
    for (int i = 0; i < 2; i++) {
        int e = tid + i * 512;              // 0..1023
        lr[i] = e >> 4; lsl[i] = (e & 15) * 8;
    }

    // activation: 1 (b,jl) pair per thread; c-state in reg
    const int b_act = tid >> 3, jl_act = tid & 7;
    float cst = 0.0f;

    for (int t = 0; t < SEQ; t++) {
        // Gx prefetch (independent of h)
        const float* gxb = g_Gx + (((size_t)t * NCTA + n) * 64 + b_act) * 32 + jl_act;
        float gx0 = gxb[0], gx1 = gxb[8], gx2 = gxb[16], gx3 = gxb[24];

        if (t > 0) {
            if (tid == 0) {
                int target = NCTA * t, v;
                do {
                    asm volatile("ld.acquire.gpu.global.s32 %0, [%1];"
                                 : "=r"(v) : "l"(&g_done) : "memory");
                } while (v < target);
            }
            __syncthreads();

            const __nv_bfloat16* Ghi = g_Hhi + (size_t)(t - 1) * 65536;
            const __nv_bfloat16* Glo = g_Hlo + (size_t)(t - 1) * 65536;

            float acc0[4] = {0.f, 0.f, 0.f, 0.f};
            float acc1[4] = {0.f, 0.f, 0.f, 0.f};

            // prologue: load + store chunk 0 into buf0
            uint4 ph[2], pl[2];
#pragma unroll
            for (int i = 0; i < 2; i++) {
                ph[i] = *(const uint4*)(Ghi + (size_t)lr[i] * 1024 + lsl[i]);
                pl[i] = *(const uint4*)(Glo + (size_t)lr[i] * 1024 + lsl[i]);
            }
            {
                __nv_bfloat16* h0 = (__nv_bfloat16*)(smem + R_HB);
                __nv_bfloat16* l0 = (__nv_bfloat16*)(smem + R_HB + 17408);
#pragma unroll
                for (int i = 0; i < 2; i++) {
                    *(uint4*)(h0 + (size_t)lr[i] * RH + lsl[i]) = ph[i];
                    *(uint4*)(l0 + (size_t)lr[i] * RH + lsl[i]) = pl[i];
                }
            }

#pragma unroll 1
            for (int ch = 0; ch < 8; ch++) {
                __syncthreads();    // buf[ch&1] ready; buf[(ch+1)&1] free
                if (ch < 7) {
                    int ko = (ch + 1) * 128;
#pragma unroll
                    for (int i = 0; i < 2; i++) {
                        ph[i] = *(const uint4*)(Ghi + (size_t)lr[i] * 1024 + ko + lsl[i]);
                        pl[i] = *(const uint4*)(Glo + (size_t)lr[i] * 1024 + ko + lsl[i]);
                    }
                }
                __nv_bfloat16* Hh = (__nv_bfloat16*)(smem + R_HB + (ch & 1) * HBUF_SZ);
                __nv_bfloat16* Hl = Hh + 8704;   // 17408 B / 2
#pragma unroll
                for (int kk = 0; kk < 4; kk++) {
                    int kid = kg * 4 + kk;
                    uint32_t ah[4], al[4], bh[4], bl[4];
                    ldmx4(ah, smem_u32(Hh + (size_t)(wm * 16 + arow) * RH + kid * 16 + akof));
                    ldmx4(al, smem_u32(Hl + (size_t)(wm * 16 + arow) * RH + kid * 16 + akof));
                    int wk = ch * 128 + kid * 16 + bkof;
                    ldmx4(bh, smem_u32(whi + (size_t)(wn * 16 + brow) * RW_STRIDE + wk));
                    ldmx4(bl, smem_u32(wlo + (size_t)(wn * 16 + brow) * RW_STRIDE + wk));
                    mma_bf16(acc0, ah, bh);
                    mma_bf16(acc1, ah, bh + 2);
                    mma_bf16(acc0, al, bh);
                    mma_bf16(acc1, al, bh + 2);
                    mma_bf16(acc0, ah, bl);
                    mma_bf16(acc1, ah, bl + 2);
                }
                if (ch < 7) {
                    __nv_bfloat16* Nh = (__nv_bfloat16*)(smem + R_HB + ((ch + 1) & 1) * HBUF_SZ);
                    __nv_bfloat16* Nl = Nh + 8704;
#pragma unroll
                    for (int i = 0; i < 2; i++) {
                        *(uint4*)(Nh + (size_t)lr[i] * RH + lsl[i]) = ph[i];
                        *(uint4*)(Nl + (size_t)lr[i] * RH + lsl[i]) = pl[i];
                    }
                }
            }

            // gate pre-activations -> gact[kg][b][c]
            {
                float* ga = gact + kg * 2176;   // 64*34
                int r0 = wm * 16 + mrow;
                int c0 = wn * 16 + ncol;
                *(float2*)(ga + (size_t)r0 * 34 + c0)            = *(float2*)&acc0[0];
                *(float2*)(ga + (size_t)(r0 + 8) * 34 + c0)      = *(float2*)&acc0[2];
                *(float2*)(ga + (size_t)r0 * 34 + c0 + 8)        = *(float2*)&acc1[0];
                *(float2*)(ga + (size_t)(r0 + 8) * 34 + c0 + 8)  = *(float2*)&acc1[2];
            }
            __syncthreads();
        }

        // ---- fused activations + cell update + h write ----
        {
            float fv = gx0, iv = gx1, ov = gx2, gv = gx3;
            if (t > 0) {
                const float* ga0 = gact + (size_t)b_act * 34 + jl_act;
                const float* ga1 = ga0 + 2176;
                fv += ga0[0]  + ga1[0];
                iv += ga0[8]  + ga1[8];
                ov += ga0[16] + ga1[16];
                gv += ga0[24] + ga1[24];
            }
            float f = sigm(fv), ii = sigm(iv), oo = sigm(ov), gt = tanhf(gv);
            cst = f * cst + ii * gt;
            float hv = oo * tanhf(cst);
            __nv_bfloat16 hh = __float2bfloat16(hv);
            size_t idx = ((size_t)t * 64 + b_act) * 1024 + n * 8 + jl_act;
            g_Hhi[idx] = hh;
            g_Hlo[idx] = __float2bfloat16(hv - __bfloat162float(hh));
        }

        __syncthreads();
        if (tid == 0)
            asm volatile("red.release.gpu.global.add.s32 [%0], %1;"
                         :: "l"(&g_done), "r"(1) : "memory");
    }
}

// ---------------- launch ----------------
extern "C" void kernel_launch(void* const* d_in, const int* in_sizes, int n_in,
                              void* d_out, int out_size) {
    const float* x  = (const float*)d_in[0];
    const float* Wf = (const float*)d_in[1];
    const float* bf = (const float*)d_in[2];
    const float* Wi = (const float*)d_in[3];
    const float* bi = (const float*)d_in[4];
    const float* Wo = (const float*)d_in[5];
    const float* bo = (const float*)d_in[6];
    const float* Wg = (const float*)d_in[7];
    const float* bg = (const float*)d_in[8];
    const float* Wy = (const float*)d_in[9];
    const float* by = (const float*)d_in[10];
    float* out = (float*)d_out;

    cudaFuncSetAttribute(k_recur, cudaFuncAttributeMaxDynamicSharedMemorySize, SMEM_R);

    k_init<<<1, 32>>>();

    // converts for the bulk GEMMs
    k_cvt<<<4096, 256>>>((const float4*)x, (long)SEQ * BATCH * IND / 4, 0);
    k_cvt_wall<<<4096, 128>>>(Wf, bf, Wi, bi, Wo, bo, Wg, bg);
    k_cvt<<<512, 256>>>((const float4*)Wy, (long)OUTD * HID / 4, 1);

    // pregemm: Gx = X @ W_all^T + b_all -> permuted [t][n][b][c]
    k_tgemm<<<dim3(32, 256), 256>>>(nullptr, nullptr, IND, 1);

    // recurrence (tensor-core, persistent)
    k_recur<<<NCTA, 512, SMEM_R>>>(Wf, Wi, Wo, Wg);

    // out = H @ Wy^T + by  (A = g_Hhi/g_Hlo written by k_recur)
    k_tgemm<<<dim3(4, 256), 256>>>(by, out, HID, 0);
}